// round 14
// baseline (speedup 1.0000x reference)
#include <cuda_runtime.h>
#include <cuda_bf16.h>
#include <cuda_fp16.h>
#include <math.h>
#include <stdint.h>

// Problem constants
#define SS  4
#define NN  32768
#define DD  256
#define KK  512
#define NHH 4
#define HDD 64
#define FF  1024
#define QKVW 768

// ---------------- scratch ----------------
__device__ float g_x   [SS*KK*DD];
__device__ int   g_cnt [SS*KK];
__device__ int   g_off [SS*KK];
__device__ int   g_cur [SS*KK];
__device__ int   g_nlist[SS*NN];
__device__ float g_y   [SS*KK*DD];
__device__ float g_qkv [SS*KK*QKVW];
__device__ float g_kv  [SS*NHH*HDD*HDD];
__device__ float g_ksum[SS*NHH*HDD];
__device__ float g_attn[SS*KK*DD];
__device__ float g_x2  [SS*KK*DD];
__device__ float g_h   [SS*KK*FF];
__device__ float g_p2  [SS*KK*DD];
__device__ float g_bqkv[QKVW];
__device__ __half g_hidf[SS*NN*DD];        // node hidden (post-gelu), fp16

// fp16 weights, [n][k]
__device__ __half g_wqkvf[QKVW*DD];
__device__ __half g_wof [DD*DD];
__device__ __half g_f1f [FF*DD];
__device__ __half g_f2f [DD*FF];
__device__ __half g_p2f [DD*DD];           // mW1[256:512]
__device__ __half g_w1f [DD*DD];           // mW1[0:256]
__device__ __half g_w2f [DD*DD];           // mW2

// ---------------- helpers ----------------
__device__ __forceinline__ float geluf(float x) {
    return 0.5f * x * (1.0f + erff(x * 0.70710678118654752440f));
}
__device__ __forceinline__ float phif(float x) {
    return x > 0.0f ? x + 1.0f : expf(x);
}
__device__ __forceinline__ uint32_t pack_hf2(float a, float b) {
    __half2 t = __floats2half2_rn(a, b);
    return *(uint32_t*)&t;
}
__device__ __forceinline__ float hflo(uint32_t p) {
    __half2 h = *(__half2*)&p; return __half2float(h.x);
}
__device__ __forceinline__ float hfhi(uint32_t p) {
    __half2 h = *(__half2*)&p; return __half2float(h.y);
}
__device__ __forceinline__ uint32_t smem_u32(const void* p) {
    uint32_t a;
    asm("{ .reg .u64 t; cvta.to.shared.u64 t, %1; cvt.u32.u64 %0, t; }" : "=r"(a) : "l"(p));
    return a;
}
#define LDSM_X4(r0, r1, r2, r3, addr) \
    asm volatile("ldmatrix.sync.aligned.m8n8.x4.shared.b16 {%0,%1,%2,%3}, [%4];" \
                 : "=r"(r0), "=r"(r1), "=r"(r2), "=r"(r3) : "r"(addr))
#define MMA_F16(d, a, b) \
    asm volatile("mma.sync.aligned.m16n8k16.row.col.f32.f16.f16.f32 " \
                 "{%0,%1,%2,%3},{%4,%5,%6,%7},{%8,%9},{%0,%1,%2,%3};" \
                 : "+f"((d)[0]), "+f"((d)[1]), "+f"((d)[2]), "+f"((d)[3]) \
                 : "r"((a)[0]), "r"((a)[1]), "r"((a)[2]), "r"((a)[3]), \
                   "r"((b)[0]), "r"((b)[1]))
#define CP_ASYNC16(dst, src) \
    asm volatile("cp.async.cg.shared.global [%0], [%1], 16;" :: "r"(dst), "l"(src))
#define CP_COMMIT() asm volatile("cp.async.commit_group;" ::: "memory")
#define CP_WAIT0()  asm volatile("cp.async.wait_group 0;" ::: "memory")

// patch GEMM smem: A hi/lo 128x32 fp16 + B 64x32 fp16, 2 stages
#define QSM_AH(s) ((s)*10240)
#define QSM_AL(s) (20480 + (s)*10240)
#define QSM_B(s)  (40960 + (s)*5120)
#define QSM_TOTAL 51200

// node GEMM smem: A resident 128x264 fp16 + B 256x40 fp16 x 2 stages
#define N1_A      0
#define N1_B(s)   (67584 + (s)*20480)
#define N1_TOTAL  108544
#define ALD 264

// ---------------- pooling ----------------
__global__ void k_count(const int* __restrict__ pid) {
    int b = blockIdx.x * blockDim.x + threadIdx.x;
    int s = b >> 15;
    atomicAdd(&g_cnt[s*KK + pid[b]], 1);
}

__global__ void k_scan() {
    __shared__ int part[256];
    int t = threadIdx.x;
    int base = t * 8;
    int loc[8];
    int sum = 0;
    #pragma unroll
    for (int i = 0; i < 8; i++) { loc[i] = sum; sum += g_cnt[base + i]; }
    part[t] = sum;
    __syncthreads();
    #pragma unroll
    for (int off = 1; off < 256; off <<= 1) {
        int v = (t >= off) ? part[t - off] : 0;
        __syncthreads();
        part[t] += v;
        __syncthreads();
    }
    int prev = (t > 0) ? part[t - 1] : 0;
    #pragma unroll
    for (int i = 0; i < 8; i++) {
        g_off[base + i] = prev + loc[i];
        g_cur[base + i] = prev + loc[i];
    }
}

__global__ void k_scatter(const int* __restrict__ pid) {
    int b = blockIdx.x * blockDim.x + threadIdx.x;
    int s = b >> 15;
    int pos = atomicAdd(&g_cur[s*KK + pid[b]], 1);
    g_nlist[pos] = b;
}

// segmented mean + fused LN1
__global__ __launch_bounds__(256) void k_patchsum(const float* __restrict__ H,
                                                  const float* __restrict__ gw,
                                                  const float* __restrict__ bw) {
    int r = blockIdx.x;
    int d = threadIdx.x;
    int cnt = g_cnt[r];
    int off = g_off[r];
    float a0 = 0.f, a1 = 0.f, a2 = 0.f, a3 = 0.f;
    int i = 0;
    for (; i + 4 <= cnt; i += 4) {
        int n0 = g_nlist[off+i],   n1 = g_nlist[off+i+1];
        int n2 = g_nlist[off+i+2], n3 = g_nlist[off+i+3];
        a0 += __ldg(&H[(size_t)n0*DD + d]);
        a1 += __ldg(&H[(size_t)n1*DD + d]);
        a2 += __ldg(&H[(size_t)n2*DD + d]);
        a3 += __ldg(&H[(size_t)n3*DD + d]);
    }
    for (; i < cnt; i++) a0 += __ldg(&H[(size_t)g_nlist[off+i]*DD + d]);
    float sum = (a0 + a1) + (a2 + a3);
    float inv = (cnt > 0) ? (1.0f / (float)cnt) : 0.0f;
    float v = sum * inv;
    g_x[(size_t)r*DD + d] = v;

    __shared__ float s1[8], s2[8];
    __shared__ float smu, sri;
    float a = v, b = v * v;
    #pragma unroll
    for (int o = 16; o > 0; o >>= 1) {
        a += __shfl_down_sync(0xffffffffu, a, o);
        b += __shfl_down_sync(0xffffffffu, b, o);
    }
    if ((d & 31) == 0) { s1[d >> 5] = a; s2[d >> 5] = b; }
    __syncthreads();
    if (d == 0) {
        float sa = 0.f, sb = 0.f;
        #pragma unroll
        for (int j = 0; j < 8; j++) { sa += s1[j]; sb += s2[j]; }
        float m   = sa * (1.0f / DD);
        float var = sb * (1.0f / DD) - m * m;
        smu = m; sri = rsqrtf(var + 1e-5f);
    }
    __syncthreads();
    g_y[(size_t)r*DD + d] = (v - smu) * sri * gw[d] + bw[d];
}

// ---------------- weight prep (also zeroes g_cnt) ----------------
__global__ void k_prep_w(const float* __restrict__ Wq, const float* __restrict__ Wk,
                         const float* __restrict__ Wv, const float* __restrict__ bq,
                         const float* __restrict__ bk, const float* __restrict__ bv,
                         const float* __restrict__ Wo, const float* __restrict__ fW1,
                         const float* __restrict__ fW2, const float* __restrict__ mW1,
                         const float* __restrict__ mW2) {
    int r = blockIdx.x, t = threadIdx.x;
    if (r < 8) g_cnt[r*256 + t] = 0;
    if (r < 768) {
        int n = r;
        float v = (n < 256) ? Wq[t*DD + n] : (n < 512) ? Wk[t*DD + (n-256)] : Wv[t*DD + (n-512)];
        g_wqkvf[n*DD + t] = __float2half(v);
        if (t == 0) g_bqkv[n] = (n < 256) ? bq[n] : (n < 512) ? bk[n-256] : bv[n-512];
    } else if (r < 1024) {
        int n = r - 768;
        g_wof[n*DD + t] = __float2half(Wo[t*DD + n]);
    } else if (r < 2048) {
        int n = r - 1024;
        g_f1f[n*DD + t] = __float2half(fW1[t*FF + n]);
    } else if (r < 2304) {
        int n = r - 2048;
        #pragma unroll
        for (int kk = 0; kk < 4; kk++) {
            int k = t + kk*256;
            g_f2f[n*FF + k] = __float2half(fW2[k*DD + n]);
        }
    } else if (r < 2560) {
        int n = r - 2304;
        g_p2f[n*DD + t] = __float2half(mW1[(256 + t)*DD + n]);
    } else if (r < 2816) {
        int n = r - 2560;
        g_w1f[n*DD + t] = __float2half(mW1[t*DD + n]);
    } else {
        int n = r - 2816;
        g_w2f[n*DD + t] = __float2half(mW2[t*DD + n]);
    }
}

// ---------------- layer norm (LN2 only) ----------------
__global__ void k_ln(const float* __restrict__ in, const float* __restrict__ gw,
                     const float* __restrict__ bw, float* __restrict__ out) {
    int r = blockIdx.x, d = threadIdx.x;
    float v = in[(size_t)r*DD + d];
    __shared__ float s1[8], s2[8];
    __shared__ float smu, sri;
    float a = v, b = v * v;
    #pragma unroll
    for (int o = 16; o > 0; o >>= 1) {
        a += __shfl_down_sync(0xffffffffu, a, o);
        b += __shfl_down_sync(0xffffffffu, b, o);
    }
    if ((d & 31) == 0) { s1[d >> 5] = a; s2[d >> 5] = b; }
    __syncthreads();
    if (d == 0) {
        float sa = 0.f, sb = 0.f;
        #pragma unroll
        for (int i = 0; i < 8; i++) { sa += s1[i]; sb += s2[i]; }
        float m   = sa * (1.0f / DD);
        float var = sb * (1.0f / DD) - m * m;
        smu = m; sri = rsqrtf(var + 1e-5f);
    }
    __syncthreads();
    out[(size_t)r*DD + d] = (v - smu) * sri * gw[d] + bw[d];
}

__global__ __launch_bounds__(256) void k_kvsum() {
    int b = blockIdx.x;
    int s = b >> 2, h = b & 3;
    int t = threadIdx.x, tx = t & 15, ty = t >> 4;
    __shared__ float ks[8][64], vs[8][64];
    float acc[4][4] = {};
    float ksl = 0.0f;
    const float* kp = g_qkv + (size_t)s*KK*QKVW + 256 + h*HDD;
    const float* vp = g_qkv + (size_t)s*KK*QKVW + 512 + h*HDD;

    for (int k0 = 0; k0 < KK; k0 += 8) {
        #pragma unroll
        for (int u = 0; u < 2; u++) {
            int idx = t + u*256; int i = idx >> 6, d = idx & 63;
            ks[i][d] = kp[(size_t)(k0 + i)*QKVW + d];
            vs[i][d] = vp[(size_t)(k0 + i)*QKVW + d];
        }
        __syncthreads();
        if (t < 64) {
            #pragma unroll
            for (int i = 0; i < 8; i++) ksl += ks[i][t];
        }
        #pragma unroll
        for (int i = 0; i < 8; i++) {
            float kd[4], ve[4];
            #pragma unroll
            for (int j = 0; j < 4; j++) { kd[j] = ks[i][ty*4+j]; ve[j] = vs[i][tx*4+j]; }
            #pragma unroll
            for (int a = 0; a < 4; a++)
                #pragma unroll
                for (int c = 0; c < 4; c++)
                    acc[a][c] += kd[a] * ve[c];
        }
        __syncthreads();
    }
    if (t < 64) g_ksum[(size_t)b*64 + t] = ksl;
    #pragma unroll
    for (int a = 0; a < 4; a++)
        #pragma unroll
        for (int c = 0; c < 4; c++)
            g_kv[((size_t)b*64 + ty*4 + a)*64 + tx*4 + c] = acc[a][c];
}

__global__ void k_attn() {
    int r = blockIdx.x;
    int s = r / KK;
    int t = threadIdx.x;
    __shared__ float qs[256];
    qs[t] = g_qkv[(size_t)r*QKVW + t];
    __syncthreads();
    int h = t >> 6, e = t & 63;
    const float* kvp = g_kv   + (size_t)(s*NHH + h)*HDD*HDD;
    const float* ksp = g_ksum + (size_t)(s*NHH + h)*HDD;
    float num = 0.f, den = 0.f;
    #pragma unroll 8
    for (int d = 0; d < 64; d++) {
        float q = qs[h*64 + d];
        num += q * kvp[d*64 + e];
        den += q * ksp[d];
    }
    g_attn[(size_t)r*DD + t] = num / (den + 1e-6f);
}

// ---- Pipelined patch GEMM (fp16 2-term), tile 128(M)x64(N), warp 32x32 ----
// modes: 0: +bias; 2: +bias+res; 5: gelu(+bias); 6: qkv epilogue
__global__ __launch_bounds__(256, 2) void k_mma_p(
    const float* __restrict__ A,
    const __half* __restrict__ Bf,
    float* __restrict__ C, int Kd, int Cld, int mode,
    const float* __restrict__ bias, const float* __restrict__ res)
{
    extern __shared__ char sm[];
    const uint32_t sb = smem_u32(sm);

    const int t = threadIdx.x, lane = t & 31, wid = t >> 5;
    const int n0 = blockIdx.x * 64, m0 = blockIdx.y * 128;
    const int wm = (wid & 3) * 32;
    const int wn = (wid >> 2) * 32;

    const int a_m = wm + (lane & 15);
    const int a_k = (lane >> 4) << 3;
    const int b_n = wn + ((lane >> 4) << 3) + (lane & 7);
    const int b_k = ((lane >> 3) & 1) << 3;

    const int ar = t >> 3, aq = t & 7;
    const int br = t >> 2, bq = t & 3;

    float acc[2][4][4] = {};
    const int nch = Kd >> 5;
    float4 apre[4];

    auto loadA = [&](int c) {
        const float* Ab = A + (size_t)m0*Kd + c*32;
        #pragma unroll
        for (int i = 0; i < 4; i++)
            apre[i] = *(const float4*)(Ab + (size_t)(ar + 32*i)*Kd + aq*4);
    };
    auto storeA = [&](int stg) {
        #pragma unroll
        for (int i = 0; i < 4; i++) {
            float4 f = apre[i];
            uint32_t h01 = pack_hf2(f.x, f.y);
            uint32_t h23 = pack_hf2(f.z, f.w);
            uint32_t l01 = pack_hf2(f.x - hflo(h01), f.y - hfhi(h01));
            uint32_t l23 = pack_hf2(f.z - hflo(h23), f.w - hfhi(h23));
            uint32_t eo = ((ar + 32*i)*40 + aq*4) * 2;
            *(uint2*)(sm + QSM_AH(stg) + eo) = make_uint2(h01, h23);
            *(uint2*)(sm + QSM_AL(stg) + eo) = make_uint2(l01, l23);
        }
    };
    auto loadB = [&](int c, int stg) {
        const int k0 = c * 32;
        uint32_t eo = (br*40 + bq*8) * 2;
        CP_ASYNC16(sb + QSM_B(stg) + eo,
                   (const void*)(Bf + (size_t)(n0 + br)*Kd + k0 + bq*8));
        CP_COMMIT();
    };

    loadA(0);
    loadB(0, 0);
    storeA(0);
    CP_WAIT0();
    __syncthreads();

    for (int c = 0; c < nch; c++) {
        const int cur = c & 1, nxt = cur ^ 1;
        const bool more = (c + 1 < nch);
        if (more) { loadA(c + 1); loadB(c + 1, nxt); }

        #pragma unroll
        for (int kk = 0; kk < 2; kk++) {
            uint32_t ah[2][4], al[2][4];
            #pragma unroll
            for (int mt = 0; mt < 2; mt++) {
                uint32_t eo = (uint32_t)((a_m + mt*16) * 40 + kk*16 + a_k) * 2;
                LDSM_X4(ah[mt][0], ah[mt][1], ah[mt][2], ah[mt][3], sb + QSM_AH(cur) + eo);
                LDSM_X4(al[mt][0], al[mt][1], al[mt][2], al[mt][3], sb + QSM_AL(cur) + eo);
            }
            #pragma unroll
            for (int g = 0; g < 2; g++) {
                uint32_t eo = (uint32_t)((b_n + g*16) * 40 + kk*16 + b_k) * 2;
                uint32_t bh[2][2];
                LDSM_X4(bh[0][0], bh[0][1], bh[1][0], bh[1][1], sb + QSM_B(cur) + eo);
                #pragma unroll
                for (int mt = 0; mt < 2; mt++) {
                    #pragma unroll
                    for (int j = 0; j < 2; j++) {
                        float* d = acc[mt][g*2 + j];
                        MMA_F16(d, ah[mt], bh[j]);
                        MMA_F16(d, al[mt], bh[j]);
                    }
                }
            }
        }
        if (more) { storeA(nxt); CP_WAIT0(); }
        __syncthreads();
    }

    const int lr = lane >> 2;
    const int lc = (lane & 3) * 2;
    #pragma unroll
    for (int mt = 0; mt < 2; mt++) {
        int mrow0 = m0 + wm + mt*16 + lr;
        int mrow1 = mrow0 + 8;
        if (mode == 2) {
            #pragma unroll
            for (int nt = 0; nt < 4; nt++) {
                int col = n0 + wn + nt*8 + lc;
                float2 bv = *(const float2*)(bias + col);
                float2 r0 = *(const float2*)(res + (size_t)mrow0*Cld + col);
                float2 r1 = *(const float2*)(res + (size_t)mrow1*Cld + col);
                float2 o0, o1;
                o0.x = acc[mt][nt][0] + bv.x + r0.x;
                o0.y = acc[mt][nt][1] + bv.y + r0.y;
                o1.x = acc[mt][nt][2] + bv.x + r1.x;
                o1.y = acc[mt][nt][3] + bv.y + r1.y;
                *(float2*)(C + (size_t)mrow0*Cld + col) = o0;
                *(float2*)(C + (size_t)mrow1*Cld + col) = o1;
            }
        } else if (mode == 5) {
            #pragma unroll
            for (int nt = 0; nt < 4; nt++) {
                int col = n0 + wn + nt*8 + lc;
                float2 bv = *(const float2*)(bias + col);
                float2 o0, o1;
                o0.x = geluf(acc[mt][nt][0] + bv.x);
                o0.y = geluf(acc[mt][nt][1] + bv.y);
                o1.x = geluf(acc[mt][nt][2] + bv.x);
                o1.y = geluf(acc[mt][nt][3] + bv.y);
                *(float2*)(C + (size_t)mrow0*Cld + col) = o0;
                *(float2*)(C + (size_t)mrow1*Cld + col) = o1;
            }
        } else if (mode == 6) {
            float mk0 = (g_cnt[mrow0] > 0) ? 1.0f : 0.0f;
            float mk1 = (g_cnt[mrow1] > 0) ? 1.0f : 0.0f;
            #pragma unroll
            for (int nt = 0; nt < 4; nt++) {
                int col = n0 + wn + nt*8 + lc;
                float2 bv = *(const float2*)(bias + col);
                float v00 = acc[mt][nt][0] + bv.x, v01 = acc[mt][nt][1] + bv.y;
                float v10 = acc[mt][nt][2] + bv.x, v11 = acc[mt][nt][3] + bv.y;
                float2 o0, o1;
                if (col < 256) {
                    o0.x = phif(v00); o0.y = phif(v01);
                    o1.x = phif(v10); o1.y = phif(v11);
                } else if (col < 512) {
                    o0.x = phif(v00) * mk0; o0.y = phif(v01) * mk0;
                    o1.x = phif(v10) * mk1; o1.y = phif(v11) * mk1;
                } else {
                    o0.x = v00 * mk0; o0.y = v01 * mk0;
                    o1.x = v10 * mk1; o1.y = v11 * mk1;
                }
                *(float2*)(C + (size_t)mrow0*Cld + col) = o0;
                *(float2*)(C + (size_t)mrow1*Cld + col) = o1;
            }
        } else { // mode 0
            #pragma unroll
            for (int nt = 0; nt < 4; nt++) {
                int col = n0 + wn + nt*8 + lc;
                float2 bv = *(const float2*)(bias + col);
                float2 o0, o1;
                o0.x = acc[mt][nt][0] + bv.x;
                o0.y = acc[mt][nt][1] + bv.y;
                o1.x = acc[mt][nt][2] + bv.x;
                o1.y = acc[mt][nt][3] + bv.y;
                *(float2*)(C + (size_t)mrow0*Cld + col) = o0;
                *(float2*)(C + (size_t)mrow1*Cld + col) = o1;
            }
        }
    }
}

// ---- Node GEMM1: tile 128x256, A (H->fp16) resident in smem, B streamed ----
// hid = gelu(A@W1f^T + p2[pid]) -> fp16
__global__ __launch_bounds__(512, 1) void k_node1(
    const float* __restrict__ H, const float* __restrict__ p2,
    const int* __restrict__ pid)
{
    extern __shared__ char sm[];
    const uint32_t sb = smem_u32(sm);

    const int t = threadIdx.x, lane = t & 31, wid = t >> 5;
    const int m0 = blockIdx.x * 128;
    const int wm = (wid & 3) * 32;
    const int wn = (wid >> 2) * 64;

    const int a_m = wm + (lane & 15);
    const int a_k = (lane >> 4) << 3;
    const int b_n = wn + ((lane >> 4) << 3) + (lane & 7);
    const int b_k = ((lane >> 3) & 1) << 3;

    // resident A: 128 rows x 256 fp16, row stride ALD=264
    #pragma unroll
    for (int i = 0; i < 16; i++) {
        int lin = t + 512*i;
        int row = lin >> 6, q = lin & 63;
        float4 f = *(const float4*)(H + (size_t)(m0 + row)*DD + q*4);
        *(uint2*)(sm + N1_A + (uint32_t)(row*ALD + q*4)*2) =
            make_uint2(pack_hf2(f.x, f.y), pack_hf2(f.z, f.w));
    }

    auto loadB = [&](int c, int stg) {
        const int k0 = c * 32;
        #pragma unroll
        for (int i = 0; i < 2; i++) {
            int idx = t + 512*i;
            int row = idx >> 2, q = idx & 3;
            CP_ASYNC16(sb + N1_B(stg) + (uint32_t)(row*40 + q*8)*2,
                       (const void*)(g_w1f + (size_t)row*DD + k0 + q*8));
        }
        CP_COMMIT();
    };

    loadB(0, 0);
    CP_WAIT0();
    __syncthreads();

    float acc[2][8][4] = {};
    for (int c = 0; c < 8; c++) {
        const int cur = c & 1, nxt = cur ^ 1;
        const bool more = (c + 1 < 8);
        if (more) loadB(c + 1, nxt);
        const int k0 = c * 32;

        #pragma unroll
        for (int kk = 0; kk < 2; kk++) {
            uint32_t ah[2][4];
            #pragma unroll
            for (int mt = 0; mt < 2; mt++) {
                uint32_t eo = (uint32_t)((a_m + mt*16)*ALD + k0 + kk*16 + a_k) * 2;
                LDSM_X4(ah[mt][0], ah[mt][1], ah[mt][2], ah[mt][3], sb + N1_A + eo);
            }
            #pragma unroll
            for (int g = 0; g < 4; g++) {
                uint32_t eo = (uint32_t)((b_n + g*16)*40 + kk*16 + b_k) * 2;
                uint32_t bh[2][2];
                LDSM_X4(bh[0][0], bh[0][1], bh[1][0], bh[1][1], sb + N1_B(cur) + eo);
                #pragma unroll
                for (int mt = 0; mt < 2; mt++) {
                    #pragma unroll
                    for (int j = 0; j < 2; j++)
                        MMA_F16(acc[mt][g*2 + j], ah[mt], bh[j]);
                }
            }
        }
        if (more) CP_WAIT0();
        __syncthreads();
    }

    const int lr = lane >> 2;
    const int lc = (lane & 3) * 2;
    #pragma unroll
    for (int mt = 0; mt < 2; mt++) {
        int mrow0 = m0 + wm + mt*16 + lr;
        int mrow1 = mrow0 + 8;
        int s0 = mrow0 >> 15, s1 = mrow1 >> 15;
        const float* p2r0 = p2 + ((size_t)(s0*KK + pid[mrow0]))*DD;
        const float* p2r1 = p2 + ((size_t)(s1*KK + pid[mrow1]))*DD;
        #pragma unroll
        for (int nt = 0; nt < 8; nt++) {
            int col = wn + nt*8 + lc;
            float v00 = geluf(acc[mt][nt][0] + p2r0[col]);
            float v01 = geluf(acc[mt][nt][1] + p2r0[col+1]);
            float v10 = geluf(acc[mt][nt][2] + p2r1[col]);
            float v11 = geluf(acc[mt][nt][3] + p2r1[col+1]);
            *(uint32_t*)&g_hidf[(size_t)mrow0*DD + col] = pack_hf2(v00, v01);
            *(uint32_t*)&g_hidf[(size_t)mrow1*DD + col] = pack_hf2(v10, v11);
        }
    }
}

// ---- Node GEMM2: tile 128x256, A (hid fp16) resident, B streamed ----
// out = hid@W2f^T + b2 + H
__global__ __launch_bounds__(512, 1) void k_node2(
    const float* __restrict__ H, const float* __restrict__ b2,
    float* __restrict__ out)
{
    extern __shared__ char sm[];
    const uint32_t sb = smem_u32(sm);

    const int t = threadIdx.x, lane = t & 31, wid = t >> 5;
    const int m0 = blockIdx.x * 128;
    const int wm = (wid & 3) * 32;
    const int wn = (wid >> 2) * 64;

    const int a_m = wm + (lane & 15);
    const int a_k = (lane >> 4) << 3;
    const int b_n = wn + ((lane >> 4) << 3) + (lane & 7);
    const int b_k = ((lane >> 3) & 1) << 3;

    auto loadB = [&](int c, int stg) {
        const int k0 = c * 32;
        #pragma unroll
        for (int i = 0; i < 2; i++) {
            int idx = t + 512*i;
            int row = idx >> 2, q = idx & 3;
            CP_ASYNC16(sb + N1_B(stg) + (uint32_t)(row*40 + q*8)*2,
                       (const void*)(g_w2f + (size_t)row*DD + k0 + q*8));
        }
        CP_COMMIT();
    };

    // resident A via cp.async: 128 rows x 256 fp16 (512B/row = 32 x 16B)
    #pragma unroll
    for (int i = 0; i < 8; i++) {
        int idx = t + 512*i;
        int row = idx >> 5, q = idx & 31;
        CP_ASYNC16(sb + N1_A + (uint32_t)(row*ALD + q*8)*2,
                   (const void*)(g_hidf + (size_t)(m0 + row)*DD + q*8));
    }
    loadB(0, 0);
    CP_COMMIT();
    CP_WAIT0();
    __syncthreads();

    float acc[2][8][4] = {};
    for (int c = 0; c < 8; c++) {
        const int cur = c & 1, nxt = cur ^ 1;
        const bool more = (c + 1 < 8);
        if (more) loadB(c + 1, nxt);
        const int k0 = c * 32;

        #pragma unroll
        for (int kk = 0; kk < 2; kk++) {
            uint32_t ah[2][4];
            #pragma unroll
            for (int mt = 0; mt < 2; mt++) {
                uint32_t eo = (uint32_t)((a_m + mt*16)*ALD + k0 + kk*16 + a_k) * 2;
                LDSM_X4(ah[mt][0], ah[mt][1], ah[mt][2], ah[mt][3], sb + N1_A + eo);
            }
            #pragma unroll
            for (int g = 0; g < 4; g++) {
                uint32_t eo = (uint32_t)((b_n + g*16)*40 + kk*16 + b_k) * 2;
                uint32_t bh[2][2];
                LDSM_X4(bh[0][0], bh[0][1], bh[1][0], bh[1][1], sb + N1_B(cur) + eo);
                #pragma unroll
                for (int mt = 0; mt < 2; mt++) {
                    #pragma unroll
                    for (int j = 0; j < 2; j++)
                        MMA_F16(acc[mt][g*2 + j], ah[mt], bh[j]);
                }
            }
        }
        if (more) CP_WAIT0();
        __syncthreads();
    }

    const int lr = lane >> 2;
    const int lc = (lane & 3) * 2;
    #pragma unroll
    for (int mt = 0; mt < 2; mt++) {
        int mrow0 = m0 + wm + mt*16 + lr;
        int mrow1 = mrow0 + 8;
        #pragma unroll
        for (int nt = 0; nt < 8; nt++) {
            int col = wn + nt*8 + lc;
            float2 bv = *(const float2*)(b2 + col);
            float2 r0 = *(const float2*)(H + (size_t)mrow0*DD + col);
            float2 r1 = *(const float2*)(H + (size_t)mrow1*DD + col);
            float2 o0, o1;
            o0.x = acc[mt][nt][0] + bv.x + r0.x;
            o0.y = acc[mt][nt][1] + bv.y + r0.y;
            o1.x = acc[mt][nt][2] + bv.x + r1.x;
            o1.y = acc[mt][nt][3] + bv.y + r1.y;
            *(float2*)(out + (size_t)mrow0*DD + col) = o0;
            *(float2*)(out + (size_t)mrow1*DD + col) = o1;
        }
    }
}

// ---------------- launch ----------------
extern "C" void kernel_launch(void* const* d_in, const int* in_sizes, int n_in,
                              void* d_out, int out_size) {
    (void)in_sizes; (void)n_in; (void)out_size;
    const float* H    = (const float*)d_in[0];
    const int*   pid  = (const int*)  d_in[1];
    const float* ln1g = (const float*)d_in[2];
    const float* ln1b = (const float*)d_in[3];
    const float* Wq   = (const float*)d_in[4];
    const float* bq   = (const float*)d_in[5];
    const float* Wk   = (const float*)d_in[6];
    const float* bk   = (const float*)d_in[7];
    const float* Wv   = (const float*)d_in[8];
    const float* bv   = (const float*)d_in[9];
    const float* Wo   = (const float*)d_in[10];
    const float* bo   = (const float*)d_in[11];
    const float* ln2g = (const float*)d_in[12];
    const float* ln2b = (const float*)d_in[13];
    const float* fW1  = (const float*)d_in[14];
    const float* fb1  = (const float*)d_in[15];
    const float* fW2  = (const float*)d_in[16];
    const float* fb2  = (const float*)d_in[17];
    const float* mW1  = (const float*)d_in[18];
    const float* mb1  = (const float*)d_in[19];
    const float* mW2  = (const float*)d_in[20];
    const float* mb2  = (const float*)d_in[21];

    float* out = (float*)d_out;
    float* psu = out + (size_t)SS*NN*DD;

    float *p_x, *p_y, *p_qkv, *p_attn, *p_x2, *p_h, *p_p2, *p_bqkv;
    __half *p_wqkvf, *p_wof, *p_f1f, *p_f2f, *p_p2f;
    cudaGetSymbolAddress((void**)&p_x,     g_x);
    cudaGetSymbolAddress((void**)&p_y,     g_y);
    cudaGetSymbolAddress((void**)&p_qkv,   g_qkv);
    cudaGetSymbolAddress((void**)&p_attn,  g_attn);
    cudaGetSymbolAddress((void**)&p_x2,    g_x2);
    cudaGetSymbolAddress((void**)&p_h,     g_h);
    cudaGetSymbolAddress((void**)&p_p2,    g_p2);
    cudaGetSymbolAddress((void**)&p_bqkv,  g_bqkv);
    cudaGetSymbolAddress((void**)&p_wqkvf, g_wqkvf);
    cudaGetSymbolAddress((void**)&p_wof,   g_wof);
    cudaGetSymbolAddress((void**)&p_f1f,   g_f1f);
    cudaGetSymbolAddress((void**)&p_f2f,   g_f2f);
    cudaGetSymbolAddress((void**)&p_p2f,   g_p2f);

    static int init_done = 0;
    if (!init_done) {
        cudaFuncSetAttribute(k_mma_p, cudaFuncAttributeMaxDynamicSharedMemorySize, QSM_TOTAL);
        cudaFuncSetAttribute(k_node1, cudaFuncAttributeMaxDynamicSharedMemorySize, N1_TOTAL);
        cudaFuncSetAttribute(k_node2, cudaFuncAttributeMaxDynamicSharedMemorySize, N1_TOTAL);
        init_done = 1;
    }

    // 1) weight prep + pooling (count-sort, LN1 fused into patchsum)
    k_prep_w<<<3072, 256>>>(Wq, Wk, Wv, bq, bk, bv, Wo, fW1, fW2, mW1, mW2);
    k_count<<<SS*NN/256, 256>>>(pid);
    k_scan<<<1, 256>>>();
    k_scatter<<<SS*NN/256, 256>>>(pid);
    k_patchsum<<<SS*KK, 256>>>(H, ln1g, ln1b);

    // 2) patch transformer (pipelined fp16 2-term GEMMs)
    k_mma_p<<<dim3(QKVW/64, (SS*KK)/128), 256, QSM_TOTAL>>>(
        p_y, p_wqkvf, p_qkv, DD, QKVW, 6, p_bqkv, nullptr);
    k_kvsum<<<SS*NHH, 256>>>();
    k_attn<<<SS*KK, 256>>>();
    k_mma_p<<<dim3(DD/64, (SS*KK)/128), 256, QSM_TOTAL>>>(
        p_attn, p_wof, p_x2, DD, DD, 2, bo, p_x);
    k_ln<<<SS*KK, 256>>>(p_x2, ln2g, ln2b, p_y);
    k_mma_p<<<dim3(FF/64, (SS*KK)/128), 256, QSM_TOTAL>>>(
        p_y, p_f1f, p_h, DD, FF, 5, fb1, nullptr);
    k_mma_p<<<dim3(DD/64, (SS*KK)/128), 256, QSM_TOTAL>>>(
        p_h, p_f2f, psu, FF, DD, 2, fb2, p_x2);

    // 3) node MLP: p2 precompute, then full-N node GEMMs (A resident)
    k_mma_p<<<dim3(DD/64, (SS*KK)/128), 256, QSM_TOTAL>>>(
        psu, p_p2f, p_p2, DD, DD, 0, mb1, nullptr);
    k_node1<<<(SS*NN)/128, 512, N1_TOTAL>>>(H, p_p2, pid);
    k_node2<<<(SS*NN)/128, 512, N1_TOTAL>>>(H, mb2, out);
}

// round 15
// speedup vs baseline: 1.0430x; 1.0430x over previous
#include <cuda_runtime.h>
#include <cuda_bf16.h>
#include <cuda_fp16.h>
#include <math.h>
#include <stdint.h>

// Problem constants
#define SS  4
#define NN  32768
#define DD  256
#define KK  512
#define NHH 4
#define HDD 64
#define FF  1024
#define QKVW 768

// ---------------- scratch ----------------
__device__ float g_x   [SS*KK*DD];
__device__ int   g_cnt [SS*KK];
__device__ int   g_off [SS*KK];
__device__ int   g_cur [SS*KK];
__device__ int   g_nlist[SS*NN];
__device__ float g_y   [SS*KK*DD];
__device__ float g_qkv [SS*KK*QKVW];
__device__ float g_kv  [SS*NHH*HDD*HDD];
__device__ float g_ksum[SS*NHH*HDD];
__device__ float g_attn[SS*KK*DD];
__device__ float g_x2  [SS*KK*DD];
__device__ float g_h   [SS*KK*FF];
__device__ float g_p2  [SS*KK*DD];
__device__ float g_bqkv[QKVW];
__device__ __half g_hidf[SS*NN*DD];        // node hidden (post-gelu), fp16

// fp16 weights, [n][k]
__device__ __half g_wqkvf[QKVW*DD];
__device__ __half g_wof [DD*DD];
__device__ __half g_f1f [FF*DD];
__device__ __half g_f2f [DD*FF];
__device__ __half g_p2f [DD*DD];           // mW1[256:512]
__device__ __half g_w1f [DD*DD];           // mW1[0:256]
__device__ __half g_w2f [DD*DD];           // mW2

// ---------------- helpers ----------------
__device__ __forceinline__ float geluf(float x) {
    return 0.5f * x * (1.0f + erff(x * 0.70710678118654752440f));
}
__device__ __forceinline__ float phif(float x) {
    return x > 0.0f ? x + 1.0f : expf(x);
}
__device__ __forceinline__ uint32_t pack_hf2(float a, float b) {
    __half2 t = __floats2half2_rn(a, b);
    return *(uint32_t*)&t;
}
__device__ __forceinline__ float hflo(uint32_t p) {
    __half2 h = *(__half2*)&p; return __half2float(h.x);
}
__device__ __forceinline__ float hfhi(uint32_t p) {
    __half2 h = *(__half2*)&p; return __half2float(h.y);
}
__device__ __forceinline__ uint32_t smem_u32(const void* p) {
    uint32_t a;
    asm("{ .reg .u64 t; cvta.to.shared.u64 t, %1; cvt.u32.u64 %0, t; }" : "=r"(a) : "l"(p));
    return a;
}
#define LDSM_X4(r0, r1, r2, r3, addr) \
    asm volatile("ldmatrix.sync.aligned.m8n8.x4.shared.b16 {%0,%1,%2,%3}, [%4];" \
                 : "=r"(r0), "=r"(r1), "=r"(r2), "=r"(r3) : "r"(addr))
#define MMA_F16(d, a, b) \
    asm volatile("mma.sync.aligned.m16n8k16.row.col.f32.f16.f16.f32 " \
                 "{%0,%1,%2,%3},{%4,%5,%6,%7},{%8,%9},{%0,%1,%2,%3};" \
                 : "+f"((d)[0]), "+f"((d)[1]), "+f"((d)[2]), "+f"((d)[3]) \
                 : "r"((a)[0]), "r"((a)[1]), "r"((a)[2]), "r"((a)[3]), \
                   "r"((b)[0]), "r"((b)[1]))
#define CP_ASYNC16(dst, src) \
    asm volatile("cp.async.cg.shared.global [%0], [%1], 16;" :: "r"(dst), "l"(src))
#define CP_COMMIT() asm volatile("cp.async.commit_group;" ::: "memory")
#define CP_WAIT0()  asm volatile("cp.async.wait_group 0;" ::: "memory")

// patch GEMM smem: A hi/lo 128x32 fp16 + B 64x32 fp16, 2 stages
#define QSM_AH(s) ((s)*10240)
#define QSM_AL(s) (20480 + (s)*10240)
#define QSM_B(s)  (40960 + (s)*5120)
#define QSM_TOTAL 51200

// node GEMM smem: K-chunk 64, A 128x72 fp16 + B 128x72 fp16, 2 stages
#define NS_A(s) ((s)*18432)
#define NS_B(s) (36864 + (s)*18432)
#define NS_TOTAL 73728
#define NLD 72

// ---------------- pooling ----------------
__global__ void k_count(const int* __restrict__ pid) {
    int b = blockIdx.x * blockDim.x + threadIdx.x;
    int s = b >> 15;
    atomicAdd(&g_cnt[s*KK + pid[b]], 1);
}

__global__ void k_scan() {
    __shared__ int part[256];
    int t = threadIdx.x;
    int base = t * 8;
    int loc[8];
    int sum = 0;
    #pragma unroll
    for (int i = 0; i < 8; i++) { loc[i] = sum; sum += g_cnt[base + i]; }
    part[t] = sum;
    __syncthreads();
    #pragma unroll
    for (int off = 1; off < 256; off <<= 1) {
        int v = (t >= off) ? part[t - off] : 0;
        __syncthreads();
        part[t] += v;
        __syncthreads();
    }
    int prev = (t > 0) ? part[t - 1] : 0;
    #pragma unroll
    for (int i = 0; i < 8; i++) {
        g_off[base + i] = prev + loc[i];
        g_cur[base + i] = prev + loc[i];
    }
}

__global__ void k_scatter(const int* __restrict__ pid) {
    int b = blockIdx.x * blockDim.x + threadIdx.x;
    int s = b >> 15;
    int pos = atomicAdd(&g_cur[s*KK + pid[b]], 1);
    g_nlist[pos] = b;
}

// segmented mean + fused LN1
__global__ __launch_bounds__(256) void k_patchsum(const float* __restrict__ H,
                                                  const float* __restrict__ gw,
                                                  const float* __restrict__ bw) {
    int r = blockIdx.x;
    int d = threadIdx.x;
    int cnt = g_cnt[r];
    int off = g_off[r];
    float a0 = 0.f, a1 = 0.f, a2 = 0.f, a3 = 0.f;
    int i = 0;
    for (; i + 4 <= cnt; i += 4) {
        int n0 = g_nlist[off+i],   n1 = g_nlist[off+i+1];
        int n2 = g_nlist[off+i+2], n3 = g_nlist[off+i+3];
        a0 += __ldg(&H[(size_t)n0*DD + d]);
        a1 += __ldg(&H[(size_t)n1*DD + d]);
        a2 += __ldg(&H[(size_t)n2*DD + d]);
        a3 += __ldg(&H[(size_t)n3*DD + d]);
    }
    for (; i < cnt; i++) a0 += __ldg(&H[(size_t)g_nlist[off+i]*DD + d]);
    float sum = (a0 + a1) + (a2 + a3);
    float inv = (cnt > 0) ? (1.0f / (float)cnt) : 0.0f;
    float v = sum * inv;
    g_x[(size_t)r*DD + d] = v;

    __shared__ float s1[8], s2[8];
    __shared__ float smu, sri;
    float a = v, b = v * v;
    #pragma unroll
    for (int o = 16; o > 0; o >>= 1) {
        a += __shfl_down_sync(0xffffffffu, a, o);
        b += __shfl_down_sync(0xffffffffu, b, o);
    }
    if ((d & 31) == 0) { s1[d >> 5] = a; s2[d >> 5] = b; }
    __syncthreads();
    if (d == 0) {
        float sa = 0.f, sb = 0.f;
        #pragma unroll
        for (int j = 0; j < 8; j++) { sa += s1[j]; sb += s2[j]; }
        float m   = sa * (1.0f / DD);
        float var = sb * (1.0f / DD) - m * m;
        smu = m; sri = rsqrtf(var + 1e-5f);
    }
    __syncthreads();
    g_y[(size_t)r*DD + d] = (v - smu) * sri * gw[d] + bw[d];
}

// ---------------- weight prep (also zeroes g_cnt) ----------------
__global__ void k_prep_w(const float* __restrict__ Wq, const float* __restrict__ Wk,
                         const float* __restrict__ Wv, const float* __restrict__ bq,
                         const float* __restrict__ bk, const float* __restrict__ bv,
                         const float* __restrict__ Wo, const float* __restrict__ fW1,
                         const float* __restrict__ fW2, const float* __restrict__ mW1,
                         const float* __restrict__ mW2) {
    int r = blockIdx.x, t = threadIdx.x;
    if (r < 8) g_cnt[r*256 + t] = 0;
    if (r < 768) {
        int n = r;
        float v = (n < 256) ? Wq[t*DD + n] : (n < 512) ? Wk[t*DD + (n-256)] : Wv[t*DD + (n-512)];
        g_wqkvf[n*DD + t] = __float2half(v);
        if (t == 0) g_bqkv[n] = (n < 256) ? bq[n] : (n < 512) ? bk[n-256] : bv[n-512];
    } else if (r < 1024) {
        int n = r - 768;
        g_wof[n*DD + t] = __float2half(Wo[t*DD + n]);
    } else if (r < 2048) {
        int n = r - 1024;
        g_f1f[n*DD + t] = __float2half(fW1[t*FF + n]);
    } else if (r < 2304) {
        int n = r - 2048;
        #pragma unroll
        for (int kk = 0; kk < 4; kk++) {
            int k = t + kk*256;
            g_f2f[n*FF + k] = __float2half(fW2[k*DD + n]);
        }
    } else if (r < 2560) {
        int n = r - 2304;
        g_p2f[n*DD + t] = __float2half(mW1[(256 + t)*DD + n]);
    } else if (r < 2816) {
        int n = r - 2560;
        g_w1f[n*DD + t] = __float2half(mW1[t*DD + n]);
    } else {
        int n = r - 2816;
        g_w2f[n*DD + t] = __float2half(mW2[t*DD + n]);
    }
}

// ---------------- layer norm (LN2 only) ----------------
__global__ void k_ln(const float* __restrict__ in, const float* __restrict__ gw,
                     const float* __restrict__ bw, float* __restrict__ out) {
    int r = blockIdx.x, d = threadIdx.x;
    float v = in[(size_t)r*DD + d];
    __shared__ float s1[8], s2[8];
    __shared__ float smu, sri;
    float a = v, b = v * v;
    #pragma unroll
    for (int o = 16; o > 0; o >>= 1) {
        a += __shfl_down_sync(0xffffffffu, a, o);
        b += __shfl_down_sync(0xffffffffu, b, o);
    }
    if ((d & 31) == 0) { s1[d >> 5] = a; s2[d >> 5] = b; }
    __syncthreads();
    if (d == 0) {
        float sa = 0.f, sb = 0.f;
        #pragma unroll
        for (int i = 0; i < 8; i++) { sa += s1[i]; sb += s2[i]; }
        float m   = sa * (1.0f / DD);
        float var = sb * (1.0f / DD) - m * m;
        smu = m; sri = rsqrtf(var + 1e-5f);
    }
    __syncthreads();
    out[(size_t)r*DD + d] = (v - smu) * sri * gw[d] + bw[d];
}

__global__ __launch_bounds__(256) void k_kvsum() {
    int b = blockIdx.x;
    int s = b >> 2, h = b & 3;
    int t = threadIdx.x, tx = t & 15, ty = t >> 4;
    __shared__ float ks[8][64], vs[8][64];
    float acc[4][4] = {};
    float ksl = 0.0f;
    const float* kp = g_qkv + (size_t)s*KK*QKVW + 256 + h*HDD;
    const float* vp = g_qkv + (size_t)s*KK*QKVW + 512 + h*HDD;

    for (int k0 = 0; k0 < KK; k0 += 8) {
        #pragma unroll
        for (int u = 0; u < 2; u++) {
            int idx = t + u*256; int i = idx >> 6, d = idx & 63;
            ks[i][d] = kp[(size_t)(k0 + i)*QKVW + d];
            vs[i][d] = vp[(size_t)(k0 + i)*QKVW + d];
        }
        __syncthreads();
        if (t < 64) {
            #pragma unroll
            for (int i = 0; i < 8; i++) ksl += ks[i][t];
        }
        #pragma unroll
        for (int i = 0; i < 8; i++) {
            float kd[4], ve[4];
            #pragma unroll
            for (int j = 0; j < 4; j++) { kd[j] = ks[i][ty*4+j]; ve[j] = vs[i][tx*4+j]; }
            #pragma unroll
            for (int a = 0; a < 4; a++)
                #pragma unroll
                for (int c = 0; c < 4; c++)
                    acc[a][c] += kd[a] * ve[c];
        }
        __syncthreads();
    }
    if (t < 64) g_ksum[(size_t)b*64 + t] = ksl;
    #pragma unroll
    for (int a = 0; a < 4; a++)
        #pragma unroll
        for (int c = 0; c < 4; c++)
            g_kv[((size_t)b*64 + ty*4 + a)*64 + tx*4 + c] = acc[a][c];
}

__global__ void k_attn() {
    int r = blockIdx.x;
    int s = r / KK;
    int t = threadIdx.x;
    __shared__ float qs[256];
    qs[t] = g_qkv[(size_t)r*QKVW + t];
    __syncthreads();
    int h = t >> 6, e = t & 63;
    const float* kvp = g_kv   + (size_t)(s*NHH + h)*HDD*HDD;
    const float* ksp = g_ksum + (size_t)(s*NHH + h)*HDD;
    float num = 0.f, den = 0.f;
    #pragma unroll 8
    for (int d = 0; d < 64; d++) {
        float q = qs[h*64 + d];
        num += q * kvp[d*64 + e];
        den += q * ksp[d];
    }
    g_attn[(size_t)r*DD + t] = num / (den + 1e-6f);
}

// ---- Pipelined patch GEMM (fp16 2-term), tile 128(M)x64(N), warp 32x32 ----
// modes: 0: +bias; 2: +bias+res; 5: gelu(+bias); 6: qkv epilogue
__global__ __launch_bounds__(256, 2) void k_mma_p(
    const float* __restrict__ A,
    const __half* __restrict__ Bf,
    float* __restrict__ C, int Kd, int Cld, int mode,
    const float* __restrict__ bias, const float* __restrict__ res)
{
    extern __shared__ char sm[];
    const uint32_t sb = smem_u32(sm);

    const int t = threadIdx.x, lane = t & 31, wid = t >> 5;
    const int n0 = blockIdx.x * 64, m0 = blockIdx.y * 128;
    const int wm = (wid & 3) * 32;
    const int wn = (wid >> 2) * 32;

    const int a_m = wm + (lane & 15);
    const int a_k = (lane >> 4) << 3;
    const int b_n = wn + ((lane >> 4) << 3) + (lane & 7);
    const int b_k = ((lane >> 3) & 1) << 3;

    const int ar = t >> 3, aq = t & 7;
    const int br = t >> 2, bq = t & 3;

    float acc[2][4][4] = {};
    const int nch = Kd >> 5;
    float4 apre[4];

    auto loadA = [&](int c) {
        const float* Ab = A + (size_t)m0*Kd + c*32;
        #pragma unroll
        for (int i = 0; i < 4; i++)
            apre[i] = *(const float4*)(Ab + (size_t)(ar + 32*i)*Kd + aq*4);
    };
    auto storeA = [&](int stg) {
        #pragma unroll
        for (int i = 0; i < 4; i++) {
            float4 f = apre[i];
            uint32_t h01 = pack_hf2(f.x, f.y);
            uint32_t h23 = pack_hf2(f.z, f.w);
            uint32_t l01 = pack_hf2(f.x - hflo(h01), f.y - hfhi(h01));
            uint32_t l23 = pack_hf2(f.z - hflo(h23), f.w - hfhi(h23));
            uint32_t eo = ((ar + 32*i)*40 + aq*4) * 2;
            *(uint2*)(sm + QSM_AH(stg) + eo) = make_uint2(h01, h23);
            *(uint2*)(sm + QSM_AL(stg) + eo) = make_uint2(l01, l23);
        }
    };
    auto loadB = [&](int c, int stg) {
        const int k0 = c * 32;
        uint32_t eo = (br*40 + bq*8) * 2;
        CP_ASYNC16(sb + QSM_B(stg) + eo,
                   (const void*)(Bf + (size_t)(n0 + br)*Kd + k0 + bq*8));
        CP_COMMIT();
    };

    loadA(0);
    loadB(0, 0);
    storeA(0);
    CP_WAIT0();
    __syncthreads();

    for (int c = 0; c < nch; c++) {
        const int cur = c & 1, nxt = cur ^ 1;
        const bool more = (c + 1 < nch);
        if (more) { loadA(c + 1); loadB(c + 1, nxt); }

        #pragma unroll
        for (int kk = 0; kk < 2; kk++) {
            uint32_t ah[2][4], al[2][4];
            #pragma unroll
            for (int mt = 0; mt < 2; mt++) {
                uint32_t eo = (uint32_t)((a_m + mt*16) * 40 + kk*16 + a_k) * 2;
                LDSM_X4(ah[mt][0], ah[mt][1], ah[mt][2], ah[mt][3], sb + QSM_AH(cur) + eo);
                LDSM_X4(al[mt][0], al[mt][1], al[mt][2], al[mt][3], sb + QSM_AL(cur) + eo);
            }
            #pragma unroll
            for (int g = 0; g < 2; g++) {
                uint32_t eo = (uint32_t)((b_n + g*16) * 40 + kk*16 + b_k) * 2;
                uint32_t bh[2][2];
                LDSM_X4(bh[0][0], bh[0][1], bh[1][0], bh[1][1], sb + QSM_B(cur) + eo);
                #pragma unroll
                for (int mt = 0; mt < 2; mt++) {
                    #pragma unroll
                    for (int j = 0; j < 2; j++) {
                        float* d = acc[mt][g*2 + j];
                        MMA_F16(d, ah[mt], bh[j]);
                        MMA_F16(d, al[mt], bh[j]);
                    }
                }
            }
        }
        if (more) { storeA(nxt); CP_WAIT0(); }
        __syncthreads();
    }

    const int lr = lane >> 2;
    const int lc = (lane & 3) * 2;
    #pragma unroll
    for (int mt = 0; mt < 2; mt++) {
        int mrow0 = m0 + wm + mt*16 + lr;
        int mrow1 = mrow0 + 8;
        if (mode == 2) {
            #pragma unroll
            for (int nt = 0; nt < 4; nt++) {
                int col = n0 + wn + nt*8 + lc;
                float2 bv = *(const float2*)(bias + col);
                float2 r0 = *(const float2*)(res + (size_t)mrow0*Cld + col);
                float2 r1 = *(const float2*)(res + (size_t)mrow1*Cld + col);
                float2 o0, o1;
                o0.x = acc[mt][nt][0] + bv.x + r0.x;
                o0.y = acc[mt][nt][1] + bv.y + r0.y;
                o1.x = acc[mt][nt][2] + bv.x + r1.x;
                o1.y = acc[mt][nt][3] + bv.y + r1.y;
                *(float2*)(C + (size_t)mrow0*Cld + col) = o0;
                *(float2*)(C + (size_t)mrow1*Cld + col) = o1;
            }
        } else if (mode == 5) {
            #pragma unroll
            for (int nt = 0; nt < 4; nt++) {
                int col = n0 + wn + nt*8 + lc;
                float2 bv = *(const float2*)(bias + col);
                float2 o0, o1;
                o0.x = geluf(acc[mt][nt][0] + bv.x);
                o0.y = geluf(acc[mt][nt][1] + bv.y);
                o1.x = geluf(acc[mt][nt][2] + bv.x);
                o1.y = geluf(acc[mt][nt][3] + bv.y);
                *(float2*)(C + (size_t)mrow0*Cld + col) = o0;
                *(float2*)(C + (size_t)mrow1*Cld + col) = o1;
            }
        } else if (mode == 6) {
            float mk0 = (g_cnt[mrow0] > 0) ? 1.0f : 0.0f;
            float mk1 = (g_cnt[mrow1] > 0) ? 1.0f : 0.0f;
            #pragma unroll
            for (int nt = 0; nt < 4; nt++) {
                int col = n0 + wn + nt*8 + lc;
                float2 bv = *(const float2*)(bias + col);
                float v00 = acc[mt][nt][0] + bv.x, v01 = acc[mt][nt][1] + bv.y;
                float v10 = acc[mt][nt][2] + bv.x, v11 = acc[mt][nt][3] + bv.y;
                float2 o0, o1;
                if (col < 256) {
                    o0.x = phif(v00); o0.y = phif(v01);
                    o1.x = phif(v10); o1.y = phif(v11);
                } else if (col < 512) {
                    o0.x = phif(v00) * mk0; o0.y = phif(v01) * mk0;
                    o1.x = phif(v10) * mk1; o1.y = phif(v11) * mk1;
                } else {
                    o0.x = v00 * mk0; o0.y = v01 * mk0;
                    o1.x = v10 * mk1; o1.y = v11 * mk1;
                }
                *(float2*)(C + (size_t)mrow0*Cld + col) = o0;
                *(float2*)(C + (size_t)mrow1*Cld + col) = o1;
            }
        } else { // mode 0
            #pragma unroll
            for (int nt = 0; nt < 4; nt++) {
                int col = n0 + wn + nt*8 + lc;
                float2 bv = *(const float2*)(bias + col);
                float2 o0, o1;
                o0.x = acc[mt][nt][0] + bv.x;
                o0.y = acc[mt][nt][1] + bv.y;
                o1.x = acc[mt][nt][2] + bv.x;
                o1.y = acc[mt][nt][3] + bv.y;
                *(float2*)(C + (size_t)mrow0*Cld + col) = o0;
                *(float2*)(C + (size_t)mrow1*Cld + col) = o1;
            }
        }
    }
}

// ---- Node GEMM1 (fp16, K-chunk 64): hid = gelu(A@W1f^T + p2[pid]) -> fp16 ----
__global__ __launch_bounds__(256, 2) void k_node1(
    const float* __restrict__ H, const float* __restrict__ p2,
    const int* __restrict__ pid)
{
    extern __shared__ char sm[];
    const uint32_t sb = smem_u32(sm);

    const int t = threadIdx.x, lane = t & 31, wid = t >> 5;
    const int n0 = blockIdx.x * 128, m0 = blockIdx.y * 128;
    const int wm = (wid & 3) * 32;
    const int wn = (wid >> 2) * 64;

    const int a_m = wm + (lane & 15);
    const int a_k = (lane >> 4) << 3;
    const int b_n = wn + ((lane >> 4) << 3) + (lane & 7);
    const int b_k = ((lane >> 3) & 1) << 3;
    const int ar = t >> 4, aq = t & 15;     // A: 16 rows/pass, 16 float4 per row
    const int br = t >> 3, bq = t & 7;      // B: 32 rows/pass, 8 x 16B per row

    float acc[2][8][4] = {};
    float4 apre[8];

    auto loadA = [&](int c) {
        const float* Ab = H + (size_t)m0*DD + c*64;
        #pragma unroll
        for (int i = 0; i < 8; i++)
            apre[i] = *(const float4*)(Ab + (size_t)(ar + 16*i)*DD + aq*4);
    };
    auto storeA = [&](int stg) {
        #pragma unroll
        for (int i = 0; i < 8; i++) {
            float4 f = apre[i];
            uint32_t eo = ((ar + 16*i)*NLD + aq*4) * 2;
            *(uint2*)(sm + NS_A(stg) + eo) =
                make_uint2(pack_hf2(f.x, f.y), pack_hf2(f.z, f.w));
        }
    };
    auto loadB = [&](int c, int stg) {
        const int k0 = c * 64;
        #pragma unroll
        for (int i = 0; i < 4; i++) {
            int row = br + 32*i;
            uint32_t eo = (row*NLD + bq*8) * 2;
            CP_ASYNC16(sb + NS_B(stg) + eo,
                       (const void*)(g_w1f + (size_t)(n0 + row)*DD + k0 + bq*8));
        }
        CP_COMMIT();
    };

    loadA(0); loadB(0, 0); storeA(0);
    CP_WAIT0();
    __syncthreads();

    for (int c = 0; c < 4; c++) {
        const int cur = c & 1, nxt = cur ^ 1;
        const bool more = (c + 1 < 4);
        if (more) { loadA(c + 1); loadB(c + 1, nxt); }

        #pragma unroll
        for (int kk = 0; kk < 4; kk++) {
            uint32_t ah[2][4];
            #pragma unroll
            for (int mt = 0; mt < 2; mt++) {
                uint32_t eo = (uint32_t)((a_m + mt*16) * NLD + kk*16 + a_k) * 2;
                LDSM_X4(ah[mt][0], ah[mt][1], ah[mt][2], ah[mt][3], sb + NS_A(cur) + eo);
            }
            #pragma unroll
            for (int g = 0; g < 4; g++) {
                uint32_t eo = (uint32_t)((b_n + g*16) * NLD + kk*16 + b_k) * 2;
                uint32_t bh[2][2];
                LDSM_X4(bh[0][0], bh[0][1], bh[1][0], bh[1][1], sb + NS_B(cur) + eo);
                #pragma unroll
                for (int mt = 0; mt < 2; mt++) {
                    #pragma unroll
                    for (int j = 0; j < 2; j++)
                        MMA_F16(acc[mt][g*2 + j], ah[mt], bh[j]);
                }
            }
        }
        if (more) { storeA(nxt); CP_WAIT0(); }
        __syncthreads();
    }

    const int lr = lane >> 2;
    const int lc = (lane & 3) * 2;
    #pragma unroll
    for (int mt = 0; mt < 2; mt++) {
        int mrow0 = m0 + wm + mt*16 + lr;
        int mrow1 = mrow0 + 8;
        int s0 = mrow0 >> 15, s1 = mrow1 >> 15;
        const float* p2r0 = p2 + ((size_t)(s0*KK + pid[mrow0]))*DD;
        const float* p2r1 = p2 + ((size_t)(s1*KK + pid[mrow1]))*DD;
        #pragma unroll
        for (int nt = 0; nt < 8; nt++) {
            int col = n0 + wn + nt*8 + lc;
            float v00 = geluf(acc[mt][nt][0] + p2r0[col]);
            float v01 = geluf(acc[mt][nt][1] + p2r0[col+1]);
            float v10 = geluf(acc[mt][nt][2] + p2r1[col]);
            float v11 = geluf(acc[mt][nt][3] + p2r1[col+1]);
            *(uint32_t*)&g_hidf[(size_t)mrow0*DD + col] = pack_hf2(v00, v01);
            *(uint32_t*)&g_hidf[(size_t)mrow1*DD + col] = pack_hf2(v10, v11);
        }
    }
}

// ---- Node GEMM2 (fp16, K-chunk 64): out = hid@W2f^T + b2 + H ----
__global__ __launch_bounds__(256, 2) void k_node2(
    const float* __restrict__ H, const float* __restrict__ b2,
    float* __restrict__ out)
{
    extern __shared__ char sm[];
    const uint32_t sb = smem_u32(sm);

    const int t = threadIdx.x, lane = t & 31, wid = t >> 5;
    const int n0 = blockIdx.x * 128, m0 = blockIdx.y * 128;
    const int wm = (wid & 3) * 32;
    const int wn = (wid >> 2) * 64;

    const int a_m = wm + (lane & 15);
    const int a_k = (lane >> 4) << 3;
    const int b_n = wn + ((lane >> 4) << 3) + (lane & 7);
    const int b_k = ((lane >> 3) & 1) << 3;
    const int br = t >> 3, bq = t & 7;

    float acc[2][8][4] = {};

    auto loadAB = [&](int c, int stg) {
        const int k0 = c * 64;
        #pragma unroll
        for (int i = 0; i < 4; i++) {
            int row = br + 32*i;
            uint32_t eo = (row*NLD + bq*8) * 2;
            CP_ASYNC16(sb + NS_A(stg) + eo,
                       (const void*)(g_hidf + (size_t)(m0 + row)*DD + k0 + bq*8));
            CP_ASYNC16(sb + NS_B(stg) + eo,
                       (const void*)(g_w2f + (size_t)(n0 + row)*DD + k0 + bq*8));
        }
        CP_COMMIT();
    };

    loadAB(0, 0);
    CP_WAIT0();
    __syncthreads();

    for (int c = 0; c < 4; c++) {
        const int cur = c & 1, nxt = cur ^ 1;
        const bool more = (c + 1 < 4);
        if (more) loadAB(c + 1, nxt);

        #pragma unroll
        for (int kk = 0; kk < 4; kk++) {
            uint32_t ah[2][4];
            #pragma unroll
            for (int mt = 0; mt < 2; mt++) {
                uint32_t eo = (uint32_t)((a_m + mt*16) * NLD + kk*16 + a_k) * 2;
                LDSM_X4(ah[mt][0], ah[mt][1], ah[mt][2], ah[mt][3], sb + NS_A(cur) + eo);
            }
            #pragma unroll
            for (int g = 0; g < 4; g++) {
                uint32_t eo = (uint32_t)((b_n + g*16) * NLD + kk*16 + b_k) * 2;
                uint32_t bh[2][2];
                LDSM_X4(bh[0][0], bh[0][1], bh[1][0], bh[1][1], sb + NS_B(cur) + eo);
                #pragma unroll
                for (int mt = 0; mt < 2; mt++) {
                    #pragma unroll
                    for (int j = 0; j < 2; j++)
                        MMA_F16(acc[mt][g*2 + j], ah[mt], bh[j]);
                }
            }
        }
        if (more) CP_WAIT0();
        __syncthreads();
    }

    const int lr = lane >> 2;
    const int lc = (lane & 3) * 2;
    #pragma unroll
    for (int mt = 0; mt < 2; mt++) {
        int mrow0 = m0 + wm + mt*16 + lr;
        int mrow1 = mrow0 + 8;
        #pragma unroll
        for (int nt = 0; nt < 8; nt++) {
            int col = n0 + wn + nt*8 + lc;
            float2 bv = *(const float2*)(b2 + col);
            float2 r0 = *(const float2*)(H + (size_t)mrow0*DD + col);
            float2 r1 = *(const float2*)(H + (size_t)mrow1*DD + col);
            float2 o0, o1;
            o0.x = acc[mt][nt][0] + bv.x + r0.x;
            o0.y = acc[mt][nt][1] + bv.y + r0.y;
            o1.x = acc[mt][nt][2] + bv.x + r1.x;
            o1.y = acc[mt][nt][3] + bv.y + r1.y;
            *(float2*)(out + (size_t)mrow0*DD + col) = o0;
            *(float2*)(out + (size_t)mrow1*DD + col) = o1;
        }
    }
}

// ---------------- launch ----------------
extern "C" void kernel_launch(void* const* d_in, const int* in_sizes, int n_in,
                              void* d_out, int out_size) {
    (void)in_sizes; (void)n_in; (void)out_size;
    const float* H    = (const float*)d_in[0];
    const int*   pid  = (const int*)  d_in[1];
    const float* ln1g = (const float*)d_in[2];
    const float* ln1b = (const float*)d_in[3];
    const float* Wq   = (const float*)d_in[4];
    const float* bq   = (const float*)d_in[5];
    const float* Wk   = (const float*)d_in[6];
    const float* bk   = (const float*)d_in[7];
    const float* Wv   = (const float*)d_in[8];
    const float* bv   = (const float*)d_in[9];
    const float* Wo   = (const float*)d_in[10];
    const float* bo   = (const float*)d_in[11];
    const float* ln2g = (const float*)d_in[12];
    const float* ln2b = (const float*)d_in[13];
    const float* fW1  = (const float*)d_in[14];
    const float* fb1  = (const float*)d_in[15];
    const float* fW2  = (const float*)d_in[16];
    const float* fb2  = (const float*)d_in[17];
    const float* mW1  = (const float*)d_in[18];
    const float* mb1  = (const float*)d_in[19];
    const float* mW2  = (const float*)d_in[20];
    const float* mb2  = (const float*)d_in[21];

    float* out = (float*)d_out;
    float* psu = out + (size_t)SS*NN*DD;

    float *p_x, *p_y, *p_qkv, *p_attn, *p_x2, *p_h, *p_p2, *p_bqkv;
    __half *p_wqkvf, *p_wof, *p_f1f, *p_f2f, *p_p2f;
    cudaGetSymbolAddress((void**)&p_x,     g_x);
    cudaGetSymbolAddress((void**)&p_y,     g_y);
    cudaGetSymbolAddress((void**)&p_qkv,   g_qkv);
    cudaGetSymbolAddress((void**)&p_attn,  g_attn);
    cudaGetSymbolAddress((void**)&p_x2,    g_x2);
    cudaGetSymbolAddress((void**)&p_h,     g_h);
    cudaGetSymbolAddress((void**)&p_p2,    g_p2);
    cudaGetSymbolAddress((void**)&p_bqkv,  g_bqkv);
    cudaGetSymbolAddress((void**)&p_wqkvf, g_wqkvf);
    cudaGetSymbolAddress((void**)&p_wof,   g_wof);
    cudaGetSymbolAddress((void**)&p_f1f,   g_f1f);
    cudaGetSymbolAddress((void**)&p_f2f,   g_f2f);
    cudaGetSymbolAddress((void**)&p_p2f,   g_p2f);

    static int init_done = 0;
    if (!init_done) {
        cudaFuncSetAttribute(k_mma_p, cudaFuncAttributeMaxDynamicSharedMemorySize, QSM_TOTAL);
        cudaFuncSetAttribute(k_node1, cudaFuncAttributeMaxDynamicSharedMemorySize, NS_TOTAL);
        cudaFuncSetAttribute(k_node2, cudaFuncAttributeMaxDynamicSharedMemorySize, NS_TOTAL);
        init_done = 1;
    }

    // 1) weight prep + pooling (count-sort, LN1 fused into patchsum)
    k_prep_w<<<3072, 256>>>(Wq, Wk, Wv, bq, bk, bv, Wo, fW1, fW2, mW1, mW2);
    k_count<<<SS*NN/256, 256>>>(pid);
    k_scan<<<1, 256>>>();
    k_scatter<<<SS*NN/256, 256>>>(pid);
    k_patchsum<<<SS*KK, 256>>>(H, ln1g, ln1b);

    // 2) patch transformer (pipelined fp16 2-term GEMMs)
    k_mma_p<<<dim3(QKVW/64, (SS*KK)/128), 256, QSM_TOTAL>>>(
        p_y, p_wqkvf, p_qkv, DD, QKVW, 6, p_bqkv, nullptr);
    k_kvsum<<<SS*NHH, 256>>>();
    k_attn<<<SS*KK, 256>>>();
    k_mma_p<<<dim3(DD/64, (SS*KK)/128), 256, QSM_TOTAL>>>(
        p_attn, p_wof, p_x2, DD, DD, 2, bo, p_x);
    k_ln<<<SS*KK, 256>>>(p_x2, ln2g, ln2b, p_y);
    k_mma_p<<<dim3(FF/64, (SS*KK)/128), 256, QSM_TOTAL>>>(
        p_y, p_f1f, p_h, DD, FF, 5, fb1, nullptr);
    k_mma_p<<<dim3(DD/64, (SS*KK)/128), 256, QSM_TOTAL>>>(
        p_h, p_f2f, psu, FF, DD, 2, fb2, p_x2);

    // 3) node MLP: p2 precompute, then fp16 node GEMMs (K-chunk 64)
    k_mma_p<<<dim3(DD/64, (SS*KK)/128), 256, QSM_TOTAL>>>(
        psu, p_p2f, p_p2, DD, DD, 0, mb1, nullptr);
    dim3 gb(DD/128, (SS*NN)/128);
    k_node1<<<gb, 256, NS_TOTAL>>>(H, p_p2, pid);
    k_node2<<<gb, 256, NS_TOTAL>>>(H, mb2, out);
}

// round 16
// speedup vs baseline: 1.0579x; 1.0143x over previous
#include <cuda_runtime.h>
#include <cuda_bf16.h>
#include <cuda_fp16.h>
#include <math.h>
#include <stdint.h>

// Problem constants
#define SS  4
#define NN  32768
#define DD  256
#define KK  512
#define NHH 4
#define HDD 64
#define FF  1024
#define QKVW 768

// ---------------- scratch ----------------
__device__ float g_x   [SS*KK*DD];
__device__ int   g_cnt [SS*KK];
__device__ int   g_off [SS*KK];
__device__ int   g_cur [SS*KK];
__device__ int   g_nlist[SS*NN];
__device__ float g_y   [SS*KK*DD];
__device__ float g_qkv [SS*KK*QKVW];
__device__ float g_kv  [SS*NHH*HDD*HDD];
__device__ float g_ksum[SS*NHH*HDD];
__device__ float g_attn[SS*KK*DD];
__device__ float g_x2  [SS*KK*DD];
__device__ float g_h   [SS*KK*FF];
__device__ float g_p2  [SS*KK*DD];
__device__ float g_bqkv[QKVW];
__device__ __half g_hidf[SS*NN*DD];        // node hidden (post-gelu), fp16

// fp16 weights, [n][k]
__device__ __half g_wqkvf[QKVW*DD];
__device__ __half g_wof [DD*DD];
__device__ __half g_f1f [FF*DD];
__device__ __half g_f2f [DD*FF];
__device__ __half g_p2f [DD*DD];           // mW1[256:512]
__device__ __half g_w1f [DD*DD];           // mW1[0:256]
__device__ __half g_w2f [DD*DD];           // mW2

// ---------------- helpers ----------------
__device__ __forceinline__ float geluf(float x) {
    return 0.5f * x * (1.0f + erff(x * 0.70710678118654752440f));
}
__device__ __forceinline__ float phif(float x) {
    return x > 0.0f ? x + 1.0f : expf(x);
}
__device__ __forceinline__ uint32_t pack_hf2(float a, float b) {
    __half2 t = __floats2half2_rn(a, b);
    return *(uint32_t*)&t;
}
__device__ __forceinline__ float hflo(uint32_t p) {
    __half2 h = *(__half2*)&p; return __half2float(h.x);
}
__device__ __forceinline__ float hfhi(uint32_t p) {
    __half2 h = *(__half2*)&p; return __half2float(h.y);
}
__device__ __forceinline__ uint32_t smem_u32(const void* p) {
    uint32_t a;
    asm("{ .reg .u64 t; cvta.to.shared.u64 t, %1; cvt.u32.u64 %0, t; }" : "=r"(a) : "l"(p));
    return a;
}
#define LDSM_X4(r0, r1, r2, r3, addr) \
    asm volatile("ldmatrix.sync.aligned.m8n8.x4.shared.b16 {%0,%1,%2,%3}, [%4];" \
                 : "=r"(r0), "=r"(r1), "=r"(r2), "=r"(r3) : "r"(addr))
#define MMA_F16(d, a, b) \
    asm volatile("mma.sync.aligned.m16n8k16.row.col.f32.f16.f16.f32 " \
                 "{%0,%1,%2,%3},{%4,%5,%6,%7},{%8,%9},{%0,%1,%2,%3};" \
                 : "+f"((d)[0]), "+f"((d)[1]), "+f"((d)[2]), "+f"((d)[3]) \
                 : "r"((a)[0]), "r"((a)[1]), "r"((a)[2]), "r"((a)[3]), \
                   "r"((b)[0]), "r"((b)[1]))
#define CP_ASYNC16(dst, src) \
    asm volatile("cp.async.cg.shared.global [%0], [%1], 16;" :: "r"(dst), "l"(src))
#define CP_COMMIT() asm volatile("cp.async.commit_group;" ::: "memory")
#define CP_WAIT0()  asm volatile("cp.async.wait_group 0;" ::: "memory")

// patch GEMM smem (K-chunk 64): A hi/lo 128x72 fp16, B 64x72 fp16, 2 stages
#define QSM_AH(s) ((s)*18432)
#define QSM_AL(s) (36864 + (s)*18432)
#define QSM_B(s)  (73728 + (s)*9216)
#define QSM_TOTAL 92160
#define QLD 72

// node GEMM smem: K-chunk 64, A 128x72 fp16 + B 128x72 fp16, 2 stages
#define NS_A(s) ((s)*18432)
#define NS_B(s) (36864 + (s)*18432)
#define NS_TOTAL 73728
#define NLD 72

// ---------------- pooling ----------------
__global__ void k_count(const int* __restrict__ pid) {
    int b = blockIdx.x * blockDim.x + threadIdx.x;
    int s = b >> 15;
    atomicAdd(&g_cnt[s*KK + pid[b]], 1);
}

__global__ void k_scan() {
    __shared__ int part[256];
    int t = threadIdx.x;
    int base = t * 8;
    int loc[8];
    int sum = 0;
    #pragma unroll
    for (int i = 0; i < 8; i++) { loc[i] = sum; sum += g_cnt[base + i]; }
    part[t] = sum;
    __syncthreads();
    #pragma unroll
    for (int off = 1; off < 256; off <<= 1) {
        int v = (t >= off) ? part[t - off] : 0;
        __syncthreads();
        part[t] += v;
        __syncthreads();
    }
    int prev = (t > 0) ? part[t - 1] : 0;
    #pragma unroll
    for (int i = 0; i < 8; i++) {
        g_off[base + i] = prev + loc[i];
        g_cur[base + i] = prev + loc[i];
    }
}

__global__ void k_scatter(const int* __restrict__ pid) {
    int b = blockIdx.x * blockDim.x + threadIdx.x;
    int s = b >> 15;
    int pos = atomicAdd(&g_cur[s*KK + pid[b]], 1);
    g_nlist[pos] = b;
}

// segmented mean + fused LN1
__global__ __launch_bounds__(256) void k_patchsum(const float* __restrict__ H,
                                                  const float* __restrict__ gw,
                                                  const float* __restrict__ bw) {
    int r = blockIdx.x;
    int d = threadIdx.x;
    int cnt = g_cnt[r];
    int off = g_off[r];
    float a0 = 0.f, a1 = 0.f, a2 = 0.f, a3 = 0.f;
    int i = 0;
    for (; i + 4 <= cnt; i += 4) {
        int n0 = g_nlist[off+i],   n1 = g_nlist[off+i+1];
        int n2 = g_nlist[off+i+2], n3 = g_nlist[off+i+3];
        a0 += __ldg(&H[(size_t)n0*DD + d]);
        a1 += __ldg(&H[(size_t)n1*DD + d]);
        a2 += __ldg(&H[(size_t)n2*DD + d]);
        a3 += __ldg(&H[(size_t)n3*DD + d]);
    }
    for (; i < cnt; i++) a0 += __ldg(&H[(size_t)g_nlist[off+i]*DD + d]);
    float sum = (a0 + a1) + (a2 + a3);
    float inv = (cnt > 0) ? (1.0f / (float)cnt) : 0.0f;
    float v = sum * inv;
    g_x[(size_t)r*DD + d] = v;

    __shared__ float s1[8], s2[8];
    __shared__ float smu, sri;
    float a = v, b = v * v;
    #pragma unroll
    for (int o = 16; o > 0; o >>= 1) {
        a += __shfl_down_sync(0xffffffffu, a, o);
        b += __shfl_down_sync(0xffffffffu, b, o);
    }
    if ((d & 31) == 0) { s1[d >> 5] = a; s2[d >> 5] = b; }
    __syncthreads();
    if (d == 0) {
        float sa = 0.f, sb = 0.f;
        #pragma unroll
        for (int j = 0; j < 8; j++) { sa += s1[j]; sb += s2[j]; }
        float m   = sa * (1.0f / DD);
        float var = sb * (1.0f / DD) - m * m;
        smu = m; sri = rsqrtf(var + 1e-5f);
    }
    __syncthreads();
    g_y[(size_t)r*DD + d] = (v - smu) * sri * gw[d] + bw[d];
}

// ---------------- weight prep (also zeroes g_cnt) ----------------
__global__ void k_prep_w(const float* __restrict__ Wq, const float* __restrict__ Wk,
                         const float* __restrict__ Wv, const float* __restrict__ bq,
                         const float* __restrict__ bk, const float* __restrict__ bv,
                         const float* __restrict__ Wo, const float* __restrict__ fW1,
                         const float* __restrict__ fW2, const float* __restrict__ mW1,
                         const float* __restrict__ mW2) {
    int r = blockIdx.x, t = threadIdx.x;
    if (r < 8) g_cnt[r*256 + t] = 0;
    if (r < 768) {
        int n = r;
        float v = (n < 256) ? Wq[t*DD + n] : (n < 512) ? Wk[t*DD + (n-256)] : Wv[t*DD + (n-512)];
        g_wqkvf[n*DD + t] = __float2half(v);
        if (t == 0) g_bqkv[n] = (n < 256) ? bq[n] : (n < 512) ? bk[n-256] : bv[n-512];
    } else if (r < 1024) {
        int n = r - 768;
        g_wof[n*DD + t] = __float2half(Wo[t*DD + n]);
    } else if (r < 2048) {
        int n = r - 1024;
        g_f1f[n*DD + t] = __float2half(fW1[t*FF + n]);
    } else if (r < 2304) {
        int n = r - 2048;
        #pragma unroll
        for (int kk = 0; kk < 4; kk++) {
            int k = t + kk*256;
            g_f2f[n*FF + k] = __float2half(fW2[k*DD + n]);
        }
    } else if (r < 2560) {
        int n = r - 2304;
        g_p2f[n*DD + t] = __float2half(mW1[(256 + t)*DD + n]);
    } else if (r < 2816) {
        int n = r - 2560;
        g_w1f[n*DD + t] = __float2half(mW1[t*DD + n]);
    } else {
        int n = r - 2816;
        g_w2f[n*DD + t] = __float2half(mW2[t*DD + n]);
    }
}

// ---------------- layer norm (LN2 only) ----------------
__global__ void k_ln(const float* __restrict__ in, const float* __restrict__ gw,
                     const float* __restrict__ bw, float* __restrict__ out) {
    int r = blockIdx.x, d = threadIdx.x;
    float v = in[(size_t)r*DD + d];
    __shared__ float s1[8], s2[8];
    __shared__ float smu, sri;
    float a = v, b = v * v;
    #pragma unroll
    for (int o = 16; o > 0; o >>= 1) {
        a += __shfl_down_sync(0xffffffffu, a, o);
        b += __shfl_down_sync(0xffffffffu, b, o);
    }
    if ((d & 31) == 0) { s1[d >> 5] = a; s2[d >> 5] = b; }
    __syncthreads();
    if (d == 0) {
        float sa = 0.f, sb = 0.f;
        #pragma unroll
        for (int i = 0; i < 8; i++) { sa += s1[i]; sb += s2[i]; }
        float m   = sa * (1.0f / DD);
        float var = sb * (1.0f / DD) - m * m;
        smu = m; sri = rsqrtf(var + 1e-5f);
    }
    __syncthreads();
    out[(size_t)r*DD + d] = (v - smu) * sri * gw[d] + bw[d];
}

__global__ __launch_bounds__(256) void k_kvsum() {
    int b = blockIdx.x;
    int s = b >> 2, h = b & 3;
    int t = threadIdx.x, tx = t & 15, ty = t >> 4;
    __shared__ float ks[8][64], vs[8][64];
    float acc[4][4] = {};
    float ksl = 0.0f;
    const float* kp = g_qkv + (size_t)s*KK*QKVW + 256 + h*HDD;
    const float* vp = g_qkv + (size_t)s*KK*QKVW + 512 + h*HDD;

    for (int k0 = 0; k0 < KK; k0 += 8) {
        #pragma unroll
        for (int u = 0; u < 2; u++) {
            int idx = t + u*256; int i = idx >> 6, d = idx & 63;
            ks[i][d] = kp[(size_t)(k0 + i)*QKVW + d];
            vs[i][d] = vp[(size_t)(k0 + i)*QKVW + d];
        }
        __syncthreads();
        if (t < 64) {
            #pragma unroll
            for (int i = 0; i < 8; i++) ksl += ks[i][t];
        }
        #pragma unroll
        for (int i = 0; i < 8; i++) {
            float kd[4], ve[4];
            #pragma unroll
            for (int j = 0; j < 4; j++) { kd[j] = ks[i][ty*4+j]; ve[j] = vs[i][tx*4+j]; }
            #pragma unroll
            for (int a = 0; a < 4; a++)
                #pragma unroll
                for (int c = 0; c < 4; c++)
                    acc[a][c] += kd[a] * ve[c];
        }
        __syncthreads();
    }
    if (t < 64) g_ksum[(size_t)b*64 + t] = ksl;
    #pragma unroll
    for (int a = 0; a < 4; a++)
        #pragma unroll
        for (int c = 0; c < 4; c++)
            g_kv[((size_t)b*64 + ty*4 + a)*64 + tx*4 + c] = acc[a][c];
}

__global__ void k_attn() {
    int r = blockIdx.x;
    int s = r / KK;
    int t = threadIdx.x;
    __shared__ float qs[256];
    qs[t] = g_qkv[(size_t)r*QKVW + t];
    __syncthreads();
    int h = t >> 6, e = t & 63;
    const float* kvp = g_kv   + (size_t)(s*NHH + h)*HDD*HDD;
    const float* ksp = g_ksum + (size_t)(s*NHH + h)*HDD;
    float num = 0.f, den = 0.f;
    #pragma unroll 8
    for (int d = 0; d < 64; d++) {
        float q = qs[h*64 + d];
        num += q * kvp[d*64 + e];
        den += q * ksp[d];
    }
    g_attn[(size_t)r*DD + t] = num / (den + 1e-6f);
}

// ---- Pipelined patch GEMM (fp16 2-term, K-chunk 64), tile 128(M)x64(N) ----
// modes: 0: +bias; 2: +bias+res; 5: gelu(+bias); 6: qkv epilogue
__global__ __launch_bounds__(256, 2) void k_mma_p(
    const float* __restrict__ A,
    const __half* __restrict__ Bf,
    float* __restrict__ C, int Kd, int Cld, int mode,
    const float* __restrict__ bias, const float* __restrict__ res)
{
    extern __shared__ char sm[];
    const uint32_t sb = smem_u32(sm);

    const int t = threadIdx.x, lane = t & 31, wid = t >> 5;
    const int n0 = blockIdx.x * 64, m0 = blockIdx.y * 128;
    const int wm = (wid & 3) * 32;
    const int wn = (wid >> 2) * 32;

    const int a_m = wm + (lane & 15);
    const int a_k = (lane >> 4) << 3;
    const int b_n = wn + ((lane >> 4) << 3) + (lane & 7);
    const int b_k = ((lane >> 3) & 1) << 3;

    const int ar = t >> 4, aq = t & 15;     // A: 16 rows/pass, 16 float4 per row
    const int br = t >> 3, bq = t & 7;      // B: 32 rows/pass, 8 x 16B per row

    float acc[2][4][4] = {};
    const int nch = Kd >> 6;
    float4 apre[8];

    auto loadA = [&](int c) {
        const float* Ab = A + (size_t)m0*Kd + c*64;
        #pragma unroll
        for (int i = 0; i < 8; i++)
            apre[i] = *(const float4*)(Ab + (size_t)(ar + 16*i)*Kd + aq*4);
    };
    auto storeA = [&](int stg) {
        #pragma unroll
        for (int i = 0; i < 8; i++) {
            float4 f = apre[i];
            uint32_t h01 = pack_hf2(f.x, f.y);
            uint32_t h23 = pack_hf2(f.z, f.w);
            uint32_t l01 = pack_hf2(f.x - hflo(h01), f.y - hfhi(h01));
            uint32_t l23 = pack_hf2(f.z - hflo(h23), f.w - hfhi(h23));
            uint32_t eo = ((ar + 16*i)*QLD + aq*4) * 2;
            *(uint2*)(sm + QSM_AH(stg) + eo) = make_uint2(h01, h23);
            *(uint2*)(sm + QSM_AL(stg) + eo) = make_uint2(l01, l23);
        }
    };
    auto loadB = [&](int c, int stg) {
        const int k0 = c * 64;
        #pragma unroll
        for (int i = 0; i < 2; i++) {
            int row = br + 32*i;
            uint32_t eo = (row*QLD + bq*8) * 2;
            CP_ASYNC16(sb + QSM_B(stg) + eo,
                       (const void*)(Bf + (size_t)(n0 + row)*Kd + k0 + bq*8));
        }
        CP_COMMIT();
    };

    loadA(0);
    loadB(0, 0);
    storeA(0);
    CP_WAIT0();
    __syncthreads();

    for (int c = 0; c < nch; c++) {
        const int cur = c & 1, nxt = cur ^ 1;
        const bool more = (c + 1 < nch);
        if (more) { loadA(c + 1); loadB(c + 1, nxt); }

        #pragma unroll
        for (int kk = 0; kk < 4; kk++) {
            uint32_t ah[2][4], al[2][4];
            #pragma unroll
            for (int mt = 0; mt < 2; mt++) {
                uint32_t eo = (uint32_t)((a_m + mt*16) * QLD + kk*16 + a_k) * 2;
                LDSM_X4(ah[mt][0], ah[mt][1], ah[mt][2], ah[mt][3], sb + QSM_AH(cur) + eo);
                LDSM_X4(al[mt][0], al[mt][1], al[mt][2], al[mt][3], sb + QSM_AL(cur) + eo);
            }
            #pragma unroll
            for (int g = 0; g < 2; g++) {
                uint32_t eo = (uint32_t)((b_n + g*16) * QLD + kk*16 + b_k) * 2;
                uint32_t bh[2][2];
                LDSM_X4(bh[0][0], bh[0][1], bh[1][0], bh[1][1], sb + QSM_B(cur) + eo);
                #pragma unroll
                for (int mt = 0; mt < 2; mt++) {
                    #pragma unroll
                    for (int j = 0; j < 2; j++) {
                        float* d = acc[mt][g*2 + j];
                        MMA_F16(d, ah[mt], bh[j]);
                        MMA_F16(d, al[mt], bh[j]);
                    }
                }
            }
        }
        if (more) { storeA(nxt); CP_WAIT0(); }
        __syncthreads();
    }

    const int lr = lane >> 2;
    const int lc = (lane & 3) * 2;
    #pragma unroll
    for (int mt = 0; mt < 2; mt++) {
        int mrow0 = m0 + wm + mt*16 + lr;
        int mrow1 = mrow0 + 8;
        if (mode == 2) {
            #pragma unroll
            for (int nt = 0; nt < 4; nt++) {
                int col = n0 + wn + nt*8 + lc;
                float2 bv = *(const float2*)(bias + col);
                float2 r0 = *(const float2*)(res + (size_t)mrow0*Cld + col);
                float2 r1 = *(const float2*)(res + (size_t)mrow1*Cld + col);
                float2 o0, o1;
                o0.x = acc[mt][nt][0] + bv.x + r0.x;
                o0.y = acc[mt][nt][1] + bv.y + r0.y;
                o1.x = acc[mt][nt][2] + bv.x + r1.x;
                o1.y = acc[mt][nt][3] + bv.y + r1.y;
                *(float2*)(C + (size_t)mrow0*Cld + col) = o0;
                *(float2*)(C + (size_t)mrow1*Cld + col) = o1;
            }
        } else if (mode == 5) {
            #pragma unroll
            for (int nt = 0; nt < 4; nt++) {
                int col = n0 + wn + nt*8 + lc;
                float2 bv = *(const float2*)(bias + col);
                float2 o0, o1;
                o0.x = geluf(acc[mt][nt][0] + bv.x);
                o0.y = geluf(acc[mt][nt][1] + bv.y);
                o1.x = geluf(acc[mt][nt][2] + bv.x);
                o1.y = geluf(acc[mt][nt][3] + bv.y);
                *(float2*)(C + (size_t)mrow0*Cld + col) = o0;
                *(float2*)(C + (size_t)mrow1*Cld + col) = o1;
            }
        } else if (mode == 6) {
            float mk0 = (g_cnt[mrow0] > 0) ? 1.0f : 0.0f;
            float mk1 = (g_cnt[mrow1] > 0) ? 1.0f : 0.0f;
            #pragma unroll
            for (int nt = 0; nt < 4; nt++) {
                int col = n0 + wn + nt*8 + lc;
                float2 bv = *(const float2*)(bias + col);
                float v00 = acc[mt][nt][0] + bv.x, v01 = acc[mt][nt][1] + bv.y;
                float v10 = acc[mt][nt][2] + bv.x, v11 = acc[mt][nt][3] + bv.y;
                float2 o0, o1;
                if (col < 256) {
                    o0.x = phif(v00); o0.y = phif(v01);
                    o1.x = phif(v10); o1.y = phif(v11);
                } else if (col < 512) {
                    o0.x = phif(v00) * mk0; o0.y = phif(v01) * mk0;
                    o1.x = phif(v10) * mk1; o1.y = phif(v11) * mk1;
                } else {
                    o0.x = v00 * mk0; o0.y = v01 * mk0;
                    o1.x = v10 * mk1; o1.y = v11 * mk1;
                }
                *(float2*)(C + (size_t)mrow0*Cld + col) = o0;
                *(float2*)(C + (size_t)mrow1*Cld + col) = o1;
            }
        } else { // mode 0
            #pragma unroll
            for (int nt = 0; nt < 4; nt++) {
                int col = n0 + wn + nt*8 + lc;
                float2 bv = *(const float2*)(bias + col);
                float2 o0, o1;
                o0.x = acc[mt][nt][0] + bv.x;
                o0.y = acc[mt][nt][1] + bv.y;
                o1.x = acc[mt][nt][2] + bv.x;
                o1.y = acc[mt][nt][3] + bv.y;
                *(float2*)(C + (size_t)mrow0*Cld + col) = o0;
                *(float2*)(C + (size_t)mrow1*Cld + col) = o1;
            }
        }
    }
}

// ---- Node GEMM1 (fp16, K-chunk 64): hid = gelu(A@W1f^T + p2[pid]) -> fp16 ----
__global__ __launch_bounds__(256, 2) void k_node1(
    const float* __restrict__ H, const float* __restrict__ p2,
    const int* __restrict__ pid)
{
    extern __shared__ char sm[];
    const uint32_t sb = smem_u32(sm);

    const int t = threadIdx.x, lane = t & 31, wid = t >> 5;
    const int n0 = blockIdx.x * 128, m0 = blockIdx.y * 128;
    const int wm = (wid & 3) * 32;
    const int wn = (wid >> 2) * 64;

    const int a_m = wm + (lane & 15);
    const int a_k = (lane >> 4) << 3;
    const int b_n = wn + ((lane >> 4) << 3) + (lane & 7);
    const int b_k = ((lane >> 3) & 1) << 3;
    const int ar = t >> 4, aq = t & 15;
    const int br = t >> 3, bq = t & 7;

    float acc[2][8][4] = {};
    float4 apre[8];

    auto loadA = [&](int c) {
        const float* Ab = H + (size_t)m0*DD + c*64;
        #pragma unroll
        for (int i = 0; i < 8; i++)
            apre[i] = *(const float4*)(Ab + (size_t)(ar + 16*i)*DD + aq*4);
    };
    auto storeA = [&](int stg) {
        #pragma unroll
        for (int i = 0; i < 8; i++) {
            float4 f = apre[i];
            uint32_t eo = ((ar + 16*i)*NLD + aq*4) * 2;
            *(uint2*)(sm + NS_A(stg) + eo) =
                make_uint2(pack_hf2(f.x, f.y), pack_hf2(f.z, f.w));
        }
    };
    auto loadB = [&](int c, int stg) {
        const int k0 = c * 64;
        #pragma unroll
        for (int i = 0; i < 4; i++) {
            int row = br + 32*i;
            uint32_t eo = (row*NLD + bq*8) * 2;
            CP_ASYNC16(sb + NS_B(stg) + eo,
                       (const void*)(g_w1f + (size_t)(n0 + row)*DD + k0 + bq*8));
        }
        CP_COMMIT();
    };

    loadA(0); loadB(0, 0); storeA(0);
    CP_WAIT0();
    __syncthreads();

    for (int c = 0; c < 4; c++) {
        const int cur = c & 1, nxt = cur ^ 1;
        const bool more = (c + 1 < 4);
        if (more) { loadA(c + 1); loadB(c + 1, nxt); }

        #pragma unroll
        for (int kk = 0; kk < 4; kk++) {
            uint32_t ah[2][4];
            #pragma unroll
            for (int mt = 0; mt < 2; mt++) {
                uint32_t eo = (uint32_t)((a_m + mt*16) * NLD + kk*16 + a_k) * 2;
                LDSM_X4(ah[mt][0], ah[mt][1], ah[mt][2], ah[mt][3], sb + NS_A(cur) + eo);
            }
            #pragma unroll
            for (int g = 0; g < 4; g++) {
                uint32_t eo = (uint32_t)((b_n + g*16) * NLD + kk*16 + b_k) * 2;
                uint32_t bh[2][2];
                LDSM_X4(bh[0][0], bh[0][1], bh[1][0], bh[1][1], sb + NS_B(cur) + eo);
                #pragma unroll
                for (int mt = 0; mt < 2; mt++) {
                    #pragma unroll
                    for (int j = 0; j < 2; j++)
                        MMA_F16(acc[mt][g*2 + j], ah[mt], bh[j]);
                }
            }
        }
        if (more) { storeA(nxt); CP_WAIT0(); }
        __syncthreads();
    }

    const int lr = lane >> 2;
    const int lc = (lane & 3) * 2;
    #pragma unroll
    for (int mt = 0; mt < 2; mt++) {
        int mrow0 = m0 + wm + mt*16 + lr;
        int mrow1 = mrow0 + 8;
        int s0 = mrow0 >> 15, s1 = mrow1 >> 15;
        const float* p2r0 = p2 + ((size_t)(s0*KK + pid[mrow0]))*DD;
        const float* p2r1 = p2 + ((size_t)(s1*KK + pid[mrow1]))*DD;
        #pragma unroll
        for (int nt = 0; nt < 8; nt++) {
            int col = n0 + wn + nt*8 + lc;
            float v00 = geluf(acc[mt][nt][0] + p2r0[col]);
            float v01 = geluf(acc[mt][nt][1] + p2r0[col+1]);
            float v10 = geluf(acc[mt][nt][2] + p2r1[col]);
            float v11 = geluf(acc[mt][nt][3] + p2r1[col+1]);
            *(uint32_t*)&g_hidf[(size_t)mrow0*DD + col] = pack_hf2(v00, v01);
            *(uint32_t*)&g_hidf[(size_t)mrow1*DD + col] = pack_hf2(v10, v11);
        }
    }
}

// ---- Node GEMM2 (fp16, K-chunk 64): out = hid@W2f^T + b2 + H ----
__global__ __launch_bounds__(256, 2) void k_node2(
    const float* __restrict__ H, const float* __restrict__ b2,
    float* __restrict__ out)
{
    extern __shared__ char sm[];
    const uint32_t sb = smem_u32(sm);

    const int t = threadIdx.x, lane = t & 31, wid = t >> 5;
    const int n0 = blockIdx.x * 128, m0 = blockIdx.y * 128;
    const int wm = (wid & 3) * 32;
    const int wn = (wid >> 2) * 64;

    const int a_m = wm + (lane & 15);
    const int a_k = (lane >> 4) << 3;
    const int b_n = wn + ((lane >> 4) << 3) + (lane & 7);
    const int b_k = ((lane >> 3) & 1) << 3;
    const int br = t >> 3, bq = t & 7;

    float acc[2][8][4] = {};

    auto loadAB = [&](int c, int stg) {
        const int k0 = c * 64;
        #pragma unroll
        for (int i = 0; i < 4; i++) {
            int row = br + 32*i;
            uint32_t eo = (row*NLD + bq*8) * 2;
            CP_ASYNC16(sb + NS_A(stg) + eo,
                       (const void*)(g_hidf + (size_t)(m0 + row)*DD + k0 + bq*8));
            CP_ASYNC16(sb + NS_B(stg) + eo,
                       (const void*)(g_w2f + (size_t)(n0 + row)*DD + k0 + bq*8));
        }
        CP_COMMIT();
    };

    loadAB(0, 0);
    CP_WAIT0();
    __syncthreads();

    for (int c = 0; c < 4; c++) {
        const int cur = c & 1, nxt = cur ^ 1;
        const bool more = (c + 1 < 4);
        if (more) loadAB(c + 1, nxt);

        #pragma unroll
        for (int kk = 0; kk < 4; kk++) {
            uint32_t ah[2][4];
            #pragma unroll
            for (int mt = 0; mt < 2; mt++) {
                uint32_t eo = (uint32_t)((a_m + mt*16) * NLD + kk*16 + a_k) * 2;
                LDSM_X4(ah[mt][0], ah[mt][1], ah[mt][2], ah[mt][3], sb + NS_A(cur) + eo);
            }
            #pragma unroll
            for (int g = 0; g < 4; g++) {
                uint32_t eo = (uint32_t)((b_n + g*16) * NLD + kk*16 + b_k) * 2;
                uint32_t bh[2][2];
                LDSM_X4(bh[0][0], bh[0][1], bh[1][0], bh[1][1], sb + NS_B(cur) + eo);
                #pragma unroll
                for (int mt = 0; mt < 2; mt++) {
                    #pragma unroll
                    for (int j = 0; j < 2; j++)
                        MMA_F16(acc[mt][g*2 + j], ah[mt], bh[j]);
                }
            }
        }
        if (more) CP_WAIT0();
        __syncthreads();
    }

    const int lr = lane >> 2;
    const int lc = (lane & 3) * 2;
    #pragma unroll
    for (int mt = 0; mt < 2; mt++) {
        int mrow0 = m0 + wm + mt*16 + lr;
        int mrow1 = mrow0 + 8;
        #pragma unroll
        for (int nt = 0; nt < 8; nt++) {
            int col = n0 + wn + nt*8 + lc;
            float2 bv = *(const float2*)(b2 + col);
            float2 r0 = *(const float2*)(H + (size_t)mrow0*DD + col);
            float2 r1 = *(const float2*)(H + (size_t)mrow1*DD + col);
            float2 o0, o1;
            o0.x = acc[mt][nt][0] + bv.x + r0.x;
            o0.y = acc[mt][nt][1] + bv.y + r0.y;
            o1.x = acc[mt][nt][2] + bv.x + r1.x;
            o1.y = acc[mt][nt][3] + bv.y + r1.y;
            *(float2*)(out + (size_t)mrow0*DD + col) = o0;
            *(float2*)(out + (size_t)mrow1*DD + col) = o1;
        }
    }
}

// ---------------- launch ----------------
extern "C" void kernel_launch(void* const* d_in, const int* in_sizes, int n_in,
                              void* d_out, int out_size) {
    (void)in_sizes; (void)n_in; (void)out_size;
    const float* H    = (const float*)d_in[0];
    const int*   pid  = (const int*)  d_in[1];
    const float* ln1g = (const float*)d_in[2];
    const float* ln1b = (const float*)d_in[3];
    const float* Wq   = (const float*)d_in[4];
    const float* bq   = (const float*)d_in[5];
    const float* Wk   = (const float*)d_in[6];
    const float* bk   = (const float*)d_in[7];
    const float* Wv   = (const float*)d_in[8];
    const float* bv   = (const float*)d_in[9];
    const float* Wo   = (const float*)d_in[10];
    const float* bo   = (const float*)d_in[11];
    const float* ln2g = (const float*)d_in[12];
    const float* ln2b = (const float*)d_in[13];
    const float* fW1  = (const float*)d_in[14];
    const float* fb1  = (const float*)d_in[15];
    const float* fW2  = (const float*)d_in[16];
    const float* fb2  = (const float*)d_in[17];
    const float* mW1  = (const float*)d_in[18];
    const float* mb1  = (const float*)d_in[19];
    const float* mW2  = (const float*)d_in[20];
    const float* mb2  = (const float*)d_in[21];

    float* out = (float*)d_out;
    float* psu = out + (size_t)SS*NN*DD;

    float *p_x, *p_y, *p_qkv, *p_attn, *p_x2, *p_h, *p_p2, *p_bqkv;
    __half *p_wqkvf, *p_wof, *p_f1f, *p_f2f, *p_p2f;
    cudaGetSymbolAddress((void**)&p_x,     g_x);
    cudaGetSymbolAddress((void**)&p_y,     g_y);
    cudaGetSymbolAddress((void**)&p_qkv,   g_qkv);
    cudaGetSymbolAddress((void**)&p_attn,  g_attn);
    cudaGetSymbolAddress((void**)&p_x2,    g_x2);
    cudaGetSymbolAddress((void**)&p_h,     g_h);
    cudaGetSymbolAddress((void**)&p_p2,    g_p2);
    cudaGetSymbolAddress((void**)&p_bqkv,  g_bqkv);
    cudaGetSymbolAddress((void**)&p_wqkvf, g_wqkvf);
    cudaGetSymbolAddress((void**)&p_wof,   g_wof);
    cudaGetSymbolAddress((void**)&p_f1f,   g_f1f);
    cudaGetSymbolAddress((void**)&p_f2f,   g_f2f);
    cudaGetSymbolAddress((void**)&p_p2f,   g_p2f);

    static int init_done = 0;
    if (!init_done) {
        cudaFuncSetAttribute(k_mma_p, cudaFuncAttributeMaxDynamicSharedMemorySize, QSM_TOTAL);
        cudaFuncSetAttribute(k_node1, cudaFuncAttributeMaxDynamicSharedMemorySize, NS_TOTAL);
        cudaFuncSetAttribute(k_node2, cudaFuncAttributeMaxDynamicSharedMemorySize, NS_TOTAL);
        init_done = 1;
    }

    // 1) weight prep + pooling (count-sort, LN1 fused into patchsum)
    k_prep_w<<<3072, 256>>>(Wq, Wk, Wv, bq, bk, bv, Wo, fW1, fW2, mW1, mW2);
    k_count<<<SS*NN/256, 256>>>(pid);
    k_scan<<<1, 256>>>();
    k_scatter<<<SS*NN/256, 256>>>(pid);
    k_patchsum<<<SS*KK, 256>>>(H, ln1g, ln1b);

    // 2) patch transformer (pipelined fp16 2-term GEMMs, K-chunk 64)
    k_mma_p<<<dim3(QKVW/64, (SS*KK)/128), 256, QSM_TOTAL>>>(
        p_y, p_wqkvf, p_qkv, DD, QKVW, 6, p_bqkv, nullptr);
    k_kvsum<<<SS*NHH, 256>>>();
    k_attn<<<SS*KK, 256>>>();
    k_mma_p<<<dim3(DD/64, (SS*KK)/128), 256, QSM_TOTAL>>>(
        p_attn, p_wof, p_x2, DD, DD, 2, bo, p_x);
    k_ln<<<SS*KK, 256>>>(p_x2, ln2g, ln2b, p_y);
    k_mma_p<<<dim3(FF/64, (SS*KK)/128), 256, QSM_TOTAL>>>(
        p_y, p_f1f, p_h, DD, FF, 5, fb1, nullptr);
    k_mma_p<<<dim3(DD/64, (SS*KK)/128), 256, QSM_TOTAL>>>(
        p_h, p_f2f, psu, FF, DD, 2, fb2, p_x2);

    // 3) node MLP: p2 precompute, then fp16 node GEMMs (K-chunk 64)
    k_mma_p<<<dim3(DD/64, (SS*KK)/128), 256, QSM_TOTAL>>>(
        psu, p_p2f, p_p2, DD, DD, 0, mb1, nullptr);
    dim3 gb(DD/128, (SS*NN)/128);
    k_node1<<<gb, 256, NS_TOTAL>>>(H, p_p2, pid);
    k_node2<<<gb, 256, NS_TOTAL>>>(H, mb2, out);
}

// round 17
// speedup vs baseline: 1.0643x; 1.0061x over previous
#include <cuda_runtime.h>
#include <cuda_bf16.h>
#include <cuda_fp16.h>
#include <math.h>
#include <stdint.h>

// Problem constants
#define SS  4
#define NN  32768
#define DD  256
#define KK  512
#define NHH 4
#define HDD 64
#define FF  1024
#define QKVW 768

// ---------------- scratch ----------------
__device__ float g_x   [SS*KK*DD];
__device__ int   g_cnt [SS*KK];
__device__ int   g_off [SS*KK];
__device__ int   g_cur [SS*KK];
__device__ int   g_nlist[SS*NN];
__device__ float g_y   [SS*KK*DD];
__device__ float g_qkv [SS*KK*QKVW];
__device__ float g_kv  [SS*NHH*HDD*HDD];
__device__ float g_ksum[SS*NHH*HDD];
__device__ float g_attn[SS*KK*DD];
__device__ float g_x2  [SS*KK*DD];
__device__ float g_h   [SS*KK*FF];
__device__ float g_p2  [SS*KK*DD];
__device__ float g_bqkv[QKVW];
__device__ __half g_hidf[SS*NN*DD];        // node hidden (post-gelu), fp16

// fp16 weights, [n][k]
__device__ __half g_wqkvf[QKVW*DD];
__device__ __half g_wof [DD*DD];
__device__ __half g_f1f [FF*DD];
__device__ __half g_f2f [DD*FF];
__device__ __half g_p2f [DD*DD];           // mW1[256:512]
__device__ __half g_w1f [DD*DD];           // mW1[0:256]
__device__ __half g_w2f [DD*DD];           // mW2

// ---------------- helpers ----------------
__device__ __forceinline__ float geluf(float x) {
    return 0.5f * x * (1.0f + erff(x * 0.70710678118654752440f));
}
__device__ __forceinline__ float phif(float x) {
    return x > 0.0f ? x + 1.0f : expf(x);
}
__device__ __forceinline__ uint32_t pack_hf2(float a, float b) {
    __half2 t = __floats2half2_rn(a, b);
    return *(uint32_t*)&t;
}
__device__ __forceinline__ float hflo(uint32_t p) {
    __half2 h = *(__half2*)&p; return __half2float(h.x);
}
__device__ __forceinline__ float hfhi(uint32_t p) {
    __half2 h = *(__half2*)&p; return __half2float(h.y);
}
__device__ __forceinline__ uint32_t smem_u32(const void* p) {
    uint32_t a;
    asm("{ .reg .u64 t; cvta.to.shared.u64 t, %1; cvt.u32.u64 %0, t; }" : "=r"(a) : "l"(p));
    return a;
}
#define LDSM_X4(r0, r1, r2, r3, addr) \
    asm volatile("ldmatrix.sync.aligned.m8n8.x4.shared.b16 {%0,%1,%2,%3}, [%4];" \
                 : "=r"(r0), "=r"(r1), "=r"(r2), "=r"(r3) : "r"(addr))
#define MMA_F16(d, a, b) \
    asm volatile("mma.sync.aligned.m16n8k16.row.col.f32.f16.f16.f32 " \
                 "{%0,%1,%2,%3},{%4,%5,%6,%7},{%8,%9},{%0,%1,%2,%3};" \
                 : "+f"((d)[0]), "+f"((d)[1]), "+f"((d)[2]), "+f"((d)[3]) \
                 : "r"((a)[0]), "r"((a)[1]), "r"((a)[2]), "r"((a)[3]), \
                   "r"((b)[0]), "r"((b)[1]))
#define CP_ASYNC16(dst, src) \
    asm volatile("cp.async.cg.shared.global [%0], [%1], 16;" :: "r"(dst), "l"(src))
#define CP_COMMIT() asm volatile("cp.async.commit_group;" ::: "memory")
#define CP_WAIT0()  asm volatile("cp.async.wait_group 0;" ::: "memory")

// patch GEMM smem (K-chunk 64): A hi/lo 128x72 fp16, B 64x72 fp16, 2 stages
#define QSM_AH(s) ((s)*18432)
#define QSM_AL(s) (36864 + (s)*18432)
#define QSM_B(s)  (73728 + (s)*9216)
#define QSM_TOTAL 92160
#define QLD 72

// M64 patch GEMM smem: A hi/lo 64x72, B 64x72, 2 stages
#define P64_AH(s) ((s)*9216)
#define P64_AL(s) (18432 + (s)*9216)
#define P64_B(s)  (36864 + (s)*9216)
#define P64_TOTAL 55296

// node GEMM smem: K-chunk 64, A 128x72 fp16 + B 128x72 fp16, 2 stages
#define NS_A(s) ((s)*18432)
#define NS_B(s) (36864 + (s)*18432)
#define NS_TOTAL 73728
#define NLD 72

// ---------------- pooling ----------------
__global__ void k_count(const int* __restrict__ pid) {
    int b = blockIdx.x * blockDim.x + threadIdx.x;
    int s = b >> 15;
    atomicAdd(&g_cnt[s*KK + pid[b]], 1);
}

__global__ void k_scan() {
    __shared__ int part[256];
    int t = threadIdx.x;
    int base = t * 8;
    int loc[8];
    int sum = 0;
    #pragma unroll
    for (int i = 0; i < 8; i++) { loc[i] = sum; sum += g_cnt[base + i]; }
    part[t] = sum;
    __syncthreads();
    #pragma unroll
    for (int off = 1; off < 256; off <<= 1) {
        int v = (t >= off) ? part[t - off] : 0;
        __syncthreads();
        part[t] += v;
        __syncthreads();
    }
    int prev = (t > 0) ? part[t - 1] : 0;
    #pragma unroll
    for (int i = 0; i < 8; i++) {
        g_off[base + i] = prev + loc[i];
        g_cur[base + i] = prev + loc[i];
    }
}

__global__ void k_scatter(const int* __restrict__ pid) {
    int b = blockIdx.x * blockDim.x + threadIdx.x;
    int s = b >> 15;
    int pos = atomicAdd(&g_cur[s*KK + pid[b]], 1);
    g_nlist[pos] = b;
}

// segmented mean + fused LN1
__global__ __launch_bounds__(256) void k_patchsum(const float* __restrict__ H,
                                                  const float* __restrict__ gw,
                                                  const float* __restrict__ bw) {
    int r = blockIdx.x;
    int d = threadIdx.x;
    int cnt = g_cnt[r];
    int off = g_off[r];
    float a0 = 0.f, a1 = 0.f, a2 = 0.f, a3 = 0.f;
    int i = 0;
    for (; i + 4 <= cnt; i += 4) {
        int n0 = g_nlist[off+i],   n1 = g_nlist[off+i+1];
        int n2 = g_nlist[off+i+2], n3 = g_nlist[off+i+3];
        a0 += __ldg(&H[(size_t)n0*DD + d]);
        a1 += __ldg(&H[(size_t)n1*DD + d]);
        a2 += __ldg(&H[(size_t)n2*DD + d]);
        a3 += __ldg(&H[(size_t)n3*DD + d]);
    }
    for (; i < cnt; i++) a0 += __ldg(&H[(size_t)g_nlist[off+i]*DD + d]);
    float sum = (a0 + a1) + (a2 + a3);
    float inv = (cnt > 0) ? (1.0f / (float)cnt) : 0.0f;
    float v = sum * inv;
    g_x[(size_t)r*DD + d] = v;

    __shared__ float s1[8], s2[8];
    __shared__ float smu, sri;
    float a = v, b = v * v;
    #pragma unroll
    for (int o = 16; o > 0; o >>= 1) {
        a += __shfl_down_sync(0xffffffffu, a, o);
        b += __shfl_down_sync(0xffffffffu, b, o);
    }
    if ((d & 31) == 0) { s1[d >> 5] = a; s2[d >> 5] = b; }
    __syncthreads();
    if (d == 0) {
        float sa = 0.f, sb = 0.f;
        #pragma unroll
        for (int j = 0; j < 8; j++) { sa += s1[j]; sb += s2[j]; }
        float m   = sa * (1.0f / DD);
        float var = sb * (1.0f / DD) - m * m;
        smu = m; sri = rsqrtf(var + 1e-5f);
    }
    __syncthreads();
    g_y[(size_t)r*DD + d] = (v - smu) * sri * gw[d] + bw[d];
}

// ---------------- weight prep (also zeroes g_cnt) ----------------
__global__ void k_prep_w(const float* __restrict__ Wq, const float* __restrict__ Wk,
                         const float* __restrict__ Wv, const float* __restrict__ bq,
                         const float* __restrict__ bk, const float* __restrict__ bv,
                         const float* __restrict__ Wo, const float* __restrict__ fW1,
                         const float* __restrict__ fW2, const float* __restrict__ mW1,
                         const float* __restrict__ mW2) {
    int r = blockIdx.x, t = threadIdx.x;
    if (r < 8) g_cnt[r*256 + t] = 0;
    if (r < 768) {
        int n = r;
        float v = (n < 256) ? Wq[t*DD + n] : (n < 512) ? Wk[t*DD + (n-256)] : Wv[t*DD + (n-512)];
        g_wqkvf[n*DD + t] = __float2half(v);
        if (t == 0) g_bqkv[n] = (n < 256) ? bq[n] : (n < 512) ? bk[n-256] : bv[n-512];
    } else if (r < 1024) {
        int n = r - 768;
        g_wof[n*DD + t] = __float2half(Wo[t*DD + n]);
    } else if (r < 2048) {
        int n = r - 1024;
        g_f1f[n*DD + t] = __float2half(fW1[t*FF + n]);
    } else if (r < 2304) {
        int n = r - 2048;
        #pragma unroll
        for (int kk = 0; kk < 4; kk++) {
            int k = t + kk*256;
            g_f2f[n*FF + k] = __float2half(fW2[k*DD + n]);
        }
    } else if (r < 2560) {
        int n = r - 2304;
        g_p2f[n*DD + t] = __float2half(mW1[(256 + t)*DD + n]);
    } else if (r < 2816) {
        int n = r - 2560;
        g_w1f[n*DD + t] = __float2half(mW1[t*DD + n]);
    } else {
        int n = r - 2816;
        g_w2f[n*DD + t] = __float2half(mW2[t*DD + n]);
    }
}

// ---------------- layer norm (LN2 only) ----------------
__global__ void k_ln(const float* __restrict__ in, const float* __restrict__ gw,
                     const float* __restrict__ bw, float* __restrict__ out) {
    int r = blockIdx.x, d = threadIdx.x;
    float v = in[(size_t)r*DD + d];
    __shared__ float s1[8], s2[8];
    __shared__ float smu, sri;
    float a = v, b = v * v;
    #pragma unroll
    for (int o = 16; o > 0; o >>= 1) {
        a += __shfl_down_sync(0xffffffffu, a, o);
        b += __shfl_down_sync(0xffffffffu, b, o);
    }
    if ((d & 31) == 0) { s1[d >> 5] = a; s2[d >> 5] = b; }
    __syncthreads();
    if (d == 0) {
        float sa = 0.f, sb = 0.f;
        #pragma unroll
        for (int i = 0; i < 8; i++) { sa += s1[i]; sb += s2[i]; }
        float m   = sa * (1.0f / DD);
        float var = sb * (1.0f / DD) - m * m;
        smu = m; sri = rsqrtf(var + 1e-5f);
    }
    __syncthreads();
    out[(size_t)r*DD + d] = (v - smu) * sri * gw[d] + bw[d];
}

__global__ __launch_bounds__(256) void k_kvsum() {
    int b = blockIdx.x;
    int s = b >> 2, h = b & 3;
    int t = threadIdx.x, tx = t & 15, ty = t >> 4;
    __shared__ float ks[8][64], vs[8][64];
    float acc[4][4] = {};
    float ksl = 0.0f;
    const float* kp = g_qkv + (size_t)s*KK*QKVW + 256 + h*HDD;
    const float* vp = g_qkv + (size_t)s*KK*QKVW + 512 + h*HDD;

    for (int k0 = 0; k0 < KK; k0 += 8) {
        #pragma unroll
        for (int u = 0; u < 2; u++) {
            int idx = t + u*256; int i = idx >> 6, d = idx & 63;
            ks[i][d] = kp[(size_t)(k0 + i)*QKVW + d];
            vs[i][d] = vp[(size_t)(k0 + i)*QKVW + d];
        }
        __syncthreads();
        if (t < 64) {
            #pragma unroll
            for (int i = 0; i < 8; i++) ksl += ks[i][t];
        }
        #pragma unroll
        for (int i = 0; i < 8; i++) {
            float kd[4], ve[4];
            #pragma unroll
            for (int j = 0; j < 4; j++) { kd[j] = ks[i][ty*4+j]; ve[j] = vs[i][tx*4+j]; }
            #pragma unroll
            for (int a = 0; a < 4; a++)
                #pragma unroll
                for (int c = 0; c < 4; c++)
                    acc[a][c] += kd[a] * ve[c];
        }
        __syncthreads();
    }
    if (t < 64) g_ksum[(size_t)b*64 + t] = ksl;
    #pragma unroll
    for (int a = 0; a < 4; a++)
        #pragma unroll
        for (int c = 0; c < 4; c++)
            g_kv[((size_t)b*64 + ty*4 + a)*64 + tx*4 + c] = acc[a][c];
}

__global__ void k_attn() {
    int r = blockIdx.x;
    int s = r / KK;
    int t = threadIdx.x;
    __shared__ float qs[256];
    qs[t] = g_qkv[(size_t)r*QKVW + t];
    __syncthreads();
    int h = t >> 6, e = t & 63;
    const float* kvp = g_kv   + (size_t)(s*NHH + h)*HDD*HDD;
    const float* ksp = g_ksum + (size_t)(s*NHH + h)*HDD;
    float num = 0.f, den = 0.f;
    #pragma unroll 8
    for (int d = 0; d < 64; d++) {
        float q = qs[h*64 + d];
        num += q * kvp[d*64 + e];
        den += q * ksp[d];
    }
    g_attn[(size_t)r*DD + t] = num / (den + 1e-6f);
}

// ---- Pipelined patch GEMM (fp16 2-term, K-chunk 64), tile 128(M)x64(N) ----
// modes: 5: gelu(+bias); 6: qkv epilogue
__global__ __launch_bounds__(256, 2) void k_mma_p(
    const float* __restrict__ A,
    const __half* __restrict__ Bf,
    float* __restrict__ C, int Kd, int Cld, int mode,
    const float* __restrict__ bias, const float* __restrict__ res)
{
    extern __shared__ char sm[];
    const uint32_t sb = smem_u32(sm);

    const int t = threadIdx.x, lane = t & 31, wid = t >> 5;
    const int n0 = blockIdx.x * 64, m0 = blockIdx.y * 128;
    const int wm = (wid & 3) * 32;
    const int wn = (wid >> 2) * 32;

    const int a_m = wm + (lane & 15);
    const int a_k = (lane >> 4) << 3;
    const int b_n = wn + ((lane >> 4) << 3) + (lane & 7);
    const int b_k = ((lane >> 3) & 1) << 3;

    const int ar = t >> 4, aq = t & 15;
    const int br = t >> 3, bq = t & 7;

    float acc[2][4][4] = {};
    const int nch = Kd >> 6;
    float4 apre[8];

    auto loadA = [&](int c) {
        const float* Ab = A + (size_t)m0*Kd + c*64;
        #pragma unroll
        for (int i = 0; i < 8; i++)
            apre[i] = *(const float4*)(Ab + (size_t)(ar + 16*i)*Kd + aq*4);
    };
    auto storeA = [&](int stg) {
        #pragma unroll
        for (int i = 0; i < 8; i++) {
            float4 f = apre[i];
            uint32_t h01 = pack_hf2(f.x, f.y);
            uint32_t h23 = pack_hf2(f.z, f.w);
            uint32_t l01 = pack_hf2(f.x - hflo(h01), f.y - hfhi(h01));
            uint32_t l23 = pack_hf2(f.z - hflo(h23), f.w - hfhi(h23));
            uint32_t eo = ((ar + 16*i)*QLD + aq*4) * 2;
            *(uint2*)(sm + QSM_AH(stg) + eo) = make_uint2(h01, h23);
            *(uint2*)(sm + QSM_AL(stg) + eo) = make_uint2(l01, l23);
        }
    };
    auto loadB = [&](int c, int stg) {
        const int k0 = c * 64;
        #pragma unroll
        for (int i = 0; i < 2; i++) {
            int row = br + 32*i;
            uint32_t eo = (row*QLD + bq*8) * 2;
            CP_ASYNC16(sb + QSM_B(stg) + eo,
                       (const void*)(Bf + (size_t)(n0 + row)*Kd + k0 + bq*8));
        }
        CP_COMMIT();
    };

    loadA(0);
    loadB(0, 0);
    storeA(0);
    CP_WAIT0();
    __syncthreads();

    for (int c = 0; c < nch; c++) {
        const int cur = c & 1, nxt = cur ^ 1;
        const bool more = (c + 1 < nch);
        if (more) { loadA(c + 1); loadB(c + 1, nxt); }

        #pragma unroll
        for (int kk = 0; kk < 4; kk++) {
            uint32_t ah[2][4], al[2][4];
            #pragma unroll
            for (int mt = 0; mt < 2; mt++) {
                uint32_t eo = (uint32_t)((a_m + mt*16) * QLD + kk*16 + a_k) * 2;
                LDSM_X4(ah[mt][0], ah[mt][1], ah[mt][2], ah[mt][3], sb + QSM_AH(cur) + eo);
                LDSM_X4(al[mt][0], al[mt][1], al[mt][2], al[mt][3], sb + QSM_AL(cur) + eo);
            }
            #pragma unroll
            for (int g = 0; g < 2; g++) {
                uint32_t eo = (uint32_t)((b_n + g*16) * QLD + kk*16 + b_k) * 2;
                uint32_t bh[2][2];
                LDSM_X4(bh[0][0], bh[0][1], bh[1][0], bh[1][1], sb + QSM_B(cur) + eo);
                #pragma unroll
                for (int mt = 0; mt < 2; mt++) {
                    #pragma unroll
                    for (int j = 0; j < 2; j++) {
                        float* d = acc[mt][g*2 + j];
                        MMA_F16(d, ah[mt], bh[j]);
                        MMA_F16(d, al[mt], bh[j]);
                    }
                }
            }
        }
        if (more) { storeA(nxt); CP_WAIT0(); }
        __syncthreads();
    }

    const int lr = lane >> 2;
    const int lc = (lane & 3) * 2;
    #pragma unroll
    for (int mt = 0; mt < 2; mt++) {
        int mrow0 = m0 + wm + mt*16 + lr;
        int mrow1 = mrow0 + 8;
        if (mode == 5) {
            #pragma unroll
            for (int nt = 0; nt < 4; nt++) {
                int col = n0 + wn + nt*8 + lc;
                float2 bv = *(const float2*)(bias + col);
                float2 o0, o1;
                o0.x = geluf(acc[mt][nt][0] + bv.x);
                o0.y = geluf(acc[mt][nt][1] + bv.y);
                o1.x = geluf(acc[mt][nt][2] + bv.x);
                o1.y = geluf(acc[mt][nt][3] + bv.y);
                *(float2*)(C + (size_t)mrow0*Cld + col) = o0;
                *(float2*)(C + (size_t)mrow1*Cld + col) = o1;
            }
        } else { // mode 6 (qkv)
            float mk0 = (g_cnt[mrow0] > 0) ? 1.0f : 0.0f;
            float mk1 = (g_cnt[mrow1] > 0) ? 1.0f : 0.0f;
            #pragma unroll
            for (int nt = 0; nt < 4; nt++) {
                int col = n0 + wn + nt*8 + lc;
                float2 bv = *(const float2*)(bias + col);
                float v00 = acc[mt][nt][0] + bv.x, v01 = acc[mt][nt][1] + bv.y;
                float v10 = acc[mt][nt][2] + bv.x, v11 = acc[mt][nt][3] + bv.y;
                float2 o0, o1;
                if (col < 256) {
                    o0.x = phif(v00); o0.y = phif(v01);
                    o1.x = phif(v10); o1.y = phif(v11);
                } else if (col < 512) {
                    o0.x = phif(v00) * mk0; o0.y = phif(v01) * mk0;
                    o1.x = phif(v10) * mk1; o1.y = phif(v11) * mk1;
                } else {
                    o0.x = v00 * mk0; o0.y = v01 * mk0;
                    o1.x = v10 * mk1; o1.y = v11 * mk1;
                }
                *(float2*)(C + (size_t)mrow0*Cld + col) = o0;
                *(float2*)(C + (size_t)mrow1*Cld + col) = o1;
            }
        }
    }
}

// ---- M64 patch GEMM (fp16 2-term, K-chunk 64), tile 64(M)x64(N), 128 thr ----
// modes: 0: +bias; 2: +bias+res
__global__ __launch_bounds__(128, 4) void k_mma_p64(
    const float* __restrict__ A,
    const __half* __restrict__ Bf,
    float* __restrict__ C, int Kd, int Cld, int mode,
    const float* __restrict__ bias, const float* __restrict__ res)
{
    extern __shared__ char sm[];
    const uint32_t sb = smem_u32(sm);

    const int t = threadIdx.x, lane = t & 31, wid = t >> 5;
    const int n0 = blockIdx.x * 64, m0 = blockIdx.y * 64;
    const int wm = (wid & 1) * 32;
    const int wn = (wid >> 1) * 32;

    const int a_m = wm + (lane & 15);
    const int a_k = (lane >> 4) << 3;
    const int b_n = wn + ((lane >> 4) << 3) + (lane & 7);
    const int b_k = ((lane >> 3) & 1) << 3;

    const int ar = t >> 4, aq = t & 15;     // A: 8 rows/pass over 8 passes
    const int br = t >> 3, bq = t & 7;      // B: 16 rows/pass over 4 passes

    float acc[2][4][4] = {};
    const int nch = Kd >> 6;
    float4 apre[8];

    auto loadA = [&](int c) {
        const float* Ab = A + (size_t)m0*Kd + c*64;
        #pragma unroll
        for (int i = 0; i < 8; i++)
            apre[i] = *(const float4*)(Ab + (size_t)(ar + 8*i)*Kd + aq*4);
    };
    auto storeA = [&](int stg) {
        #pragma unroll
        for (int i = 0; i < 8; i++) {
            float4 f = apre[i];
            uint32_t h01 = pack_hf2(f.x, f.y);
            uint32_t h23 = pack_hf2(f.z, f.w);
            uint32_t l01 = pack_hf2(f.x - hflo(h01), f.y - hfhi(h01));
            uint32_t l23 = pack_hf2(f.z - hflo(h23), f.w - hfhi(h23));
            uint32_t eo = ((ar + 8*i)*QLD + aq*4) * 2;
            *(uint2*)(sm + P64_AH(stg) + eo) = make_uint2(h01, h23);
            *(uint2*)(sm + P64_AL(stg) + eo) = make_uint2(l01, l23);
        }
    };
    auto loadB = [&](int c, int stg) {
        const int k0 = c * 64;
        #pragma unroll
        for (int i = 0; i < 4; i++) {
            int row = br + 16*i;
            uint32_t eo = (row*QLD + bq*8) * 2;
            CP_ASYNC16(sb + P64_B(stg) + eo,
                       (const void*)(Bf + (size_t)(n0 + row)*Kd + k0 + bq*8));
        }
        CP_COMMIT();
    };

    loadA(0);
    loadB(0, 0);
    storeA(0);
    CP_WAIT0();
    __syncthreads();

    for (int c = 0; c < nch; c++) {
        const int cur = c & 1, nxt = cur ^ 1;
        const bool more = (c + 1 < nch);
        if (more) { loadA(c + 1); loadB(c + 1, nxt); }

        #pragma unroll
        for (int kk = 0; kk < 4; kk++) {
            uint32_t ah[2][4], al[2][4];
            #pragma unroll
            for (int mt = 0; mt < 2; mt++) {
                uint32_t eo = (uint32_t)((a_m + mt*16) * QLD + kk*16 + a_k) * 2;
                LDSM_X4(ah[mt][0], ah[mt][1], ah[mt][2], ah[mt][3], sb + P64_AH(cur) + eo);
                LDSM_X4(al[mt][0], al[mt][1], al[mt][2], al[mt][3], sb + P64_AL(cur) + eo);
            }
            #pragma unroll
            for (int g = 0; g < 2; g++) {
                uint32_t eo = (uint32_t)((b_n + g*16) * QLD + kk*16 + b_k) * 2;
                uint32_t bh[2][2];
                LDSM_X4(bh[0][0], bh[0][1], bh[1][0], bh[1][1], sb + P64_B(cur) + eo);
                #pragma unroll
                for (int mt = 0; mt < 2; mt++) {
                    #pragma unroll
                    for (int j = 0; j < 2; j++) {
                        float* d = acc[mt][g*2 + j];
                        MMA_F16(d, ah[mt], bh[j]);
                        MMA_F16(d, al[mt], bh[j]);
                    }
                }
            }
        }
        if (more) { storeA(nxt); CP_WAIT0(); }
        __syncthreads();
    }

    const int lr = lane >> 2;
    const int lc = (lane & 3) * 2;
    #pragma unroll
    for (int mt = 0; mt < 2; mt++) {
        int mrow0 = m0 + wm + mt*16 + lr;
        int mrow1 = mrow0 + 8;
        if (mode == 2) {
            #pragma unroll
            for (int nt = 0; nt < 4; nt++) {
                int col = n0 + wn + nt*8 + lc;
                float2 bv = *(const float2*)(bias + col);
                float2 r0 = *(const float2*)(res + (size_t)mrow0*Cld + col);
                float2 r1 = *(const float2*)(res + (size_t)mrow1*Cld + col);
                float2 o0, o1;
                o0.x = acc[mt][nt][0] + bv.x + r0.x;
                o0.y = acc[mt][nt][1] + bv.y + r0.y;
                o1.x = acc[mt][nt][2] + bv.x + r1.x;
                o1.y = acc[mt][nt][3] + bv.y + r1.y;
                *(float2*)(C + (size_t)mrow0*Cld + col) = o0;
                *(float2*)(C + (size_t)mrow1*Cld + col) = o1;
            }
        } else { // mode 0
            #pragma unroll
            for (int nt = 0; nt < 4; nt++) {
                int col = n0 + wn + nt*8 + lc;
                float2 bv = *(const float2*)(bias + col);
                float2 o0, o1;
                o0.x = acc[mt][nt][0] + bv.x;
                o0.y = acc[mt][nt][1] + bv.y;
                o1.x = acc[mt][nt][2] + bv.x;
                o1.y = acc[mt][nt][3] + bv.y;
                *(float2*)(C + (size_t)mrow0*Cld + col) = o0;
                *(float2*)(C + (size_t)mrow1*Cld + col) = o1;
            }
        }
    }
}

// ---- Node GEMM1 (fp16, K-chunk 64): hid = gelu(A@W1f^T + p2[pid]) -> fp16 ----
__global__ __launch_bounds__(256, 2) void k_node1(
    const float* __restrict__ H, const float* __restrict__ p2,
    const int* __restrict__ pid)
{
    extern __shared__ char sm[];
    const uint32_t sb = smem_u32(sm);

    const int t = threadIdx.x, lane = t & 31, wid = t >> 5;
    const int n0 = blockIdx.x * 128, m0 = blockIdx.y * 128;
    const int wm = (wid & 3) * 32;
    const int wn = (wid >> 2) * 64;

    const int a_m = wm + (lane & 15);
    const int a_k = (lane >> 4) << 3;
    const int b_n = wn + ((lane >> 4) << 3) + (lane & 7);
    const int b_k = ((lane >> 3) & 1) << 3;
    const int ar = t >> 4, aq = t & 15;
    const int br = t >> 3, bq = t & 7;

    float acc[2][8][4] = {};
    float4 apre[8];

    auto loadA = [&](int c) {
        const float* Ab = H + (size_t)m0*DD + c*64;
        #pragma unroll
        for (int i = 0; i < 8; i++)
            apre[i] = *(const float4*)(Ab + (size_t)(ar + 16*i)*DD + aq*4);
    };
    auto storeA = [&](int stg) {
        #pragma unroll
        for (int i = 0; i < 8; i++) {
            float4 f = apre[i];
            uint32_t eo = ((ar + 16*i)*NLD + aq*4) * 2;
            *(uint2*)(sm + NS_A(stg) + eo) =
                make_uint2(pack_hf2(f.x, f.y), pack_hf2(f.z, f.w));
        }
    };
    auto loadB = [&](int c, int stg) {
        const int k0 = c * 64;
        #pragma unroll
        for (int i = 0; i < 4; i++) {
            int row = br + 32*i;
            uint32_t eo = (row*NLD + bq*8) * 2;
            CP_ASYNC16(sb + NS_B(stg) + eo,
                       (const void*)(g_w1f + (size_t)(n0 + row)*DD + k0 + bq*8));
        }
        CP_COMMIT();
    };

    loadA(0); loadB(0, 0); storeA(0);
    CP_WAIT0();
    __syncthreads();

    for (int c = 0; c < 4; c++) {
        const int cur = c & 1, nxt = cur ^ 1;
        const bool more = (c + 1 < 4);
        if (more) { loadA(c + 1); loadB(c + 1, nxt); }

        #pragma unroll
        for (int kk = 0; kk < 4; kk++) {
            uint32_t ah[2][4];
            #pragma unroll
            for (int mt = 0; mt < 2; mt++) {
                uint32_t eo = (uint32_t)((a_m + mt*16) * NLD + kk*16 + a_k) * 2;
                LDSM_X4(ah[mt][0], ah[mt][1], ah[mt][2], ah[mt][3], sb + NS_A(cur) + eo);
            }
            #pragma unroll
            for (int g = 0; g < 4; g++) {
                uint32_t eo = (uint32_t)((b_n + g*16) * NLD + kk*16 + b_k) * 2;
                uint32_t bh[2][2];
                LDSM_X4(bh[0][0], bh[0][1], bh[1][0], bh[1][1], sb + NS_B(cur) + eo);
                #pragma unroll
                for (int mt = 0; mt < 2; mt++) {
                    #pragma unroll
                    for (int j = 0; j < 2; j++)
                        MMA_F16(acc[mt][g*2 + j], ah[mt], bh[j]);
                }
            }
        }
        if (more) { storeA(nxt); CP_WAIT0(); }
        __syncthreads();
    }

    const int lr = lane >> 2;
    const int lc = (lane & 3) * 2;
    #pragma unroll
    for (int mt = 0; mt < 2; mt++) {
        int mrow0 = m0 + wm + mt*16 + lr;
        int mrow1 = mrow0 + 8;
        int s0 = mrow0 >> 15, s1 = mrow1 >> 15;
        const float* p2r0 = p2 + ((size_t)(s0*KK + pid[mrow0]))*DD;
        const float* p2r1 = p2 + ((size_t)(s1*KK + pid[mrow1]))*DD;
        #pragma unroll
        for (int nt = 0; nt < 8; nt++) {
            int col = n0 + wn + nt*8 + lc;
            float v00 = geluf(acc[mt][nt][0] + p2r0[col]);
            float v01 = geluf(acc[mt][nt][1] + p2r0[col+1]);
            float v10 = geluf(acc[mt][nt][2] + p2r1[col]);
            float v11 = geluf(acc[mt][nt][3] + p2r1[col+1]);
            *(uint32_t*)&g_hidf[(size_t)mrow0*DD + col] = pack_hf2(v00, v01);
            *(uint32_t*)&g_hidf[(size_t)mrow1*DD + col] = pack_hf2(v10, v11);
        }
    }
}

// ---- Node GEMM2 (fp16, K-chunk 64): out = hid@W2f^T + b2 + H ----
__global__ __launch_bounds__(256, 2) void k_node2(
    const float* __restrict__ H, const float* __restrict__ b2,
    float* __restrict__ out)
{
    extern __shared__ char sm[];
    const uint32_t sb = smem_u32(sm);

    const int t = threadIdx.x, lane = t & 31, wid = t >> 5;
    const int n0 = blockIdx.x * 128, m0 = blockIdx.y * 128;
    const int wm = (wid & 3) * 32;
    const int wn = (wid >> 2) * 64;

    const int a_m = wm + (lane & 15);
    const int a_k = (lane >> 4) << 3;
    const int b_n = wn + ((lane >> 4) << 3) + (lane & 7);
    const int b_k = ((lane >> 3) & 1) << 3;
    const int br = t >> 3, bq = t & 7;

    float acc[2][8][4] = {};

    auto loadAB = [&](int c, int stg) {
        const int k0 = c * 64;
        #pragma unroll
        for (int i = 0; i < 4; i++) {
            int row = br + 32*i;
            uint32_t eo = (row*NLD + bq*8) * 2;
            CP_ASYNC16(sb + NS_A(stg) + eo,
                       (const void*)(g_hidf + (size_t)(m0 + row)*DD + k0 + bq*8));
            CP_ASYNC16(sb + NS_B(stg) + eo,
                       (const void*)(g_w2f + (size_t)(n0 + row)*DD + k0 + bq*8));
        }
        CP_COMMIT();
    };

    loadAB(0, 0);
    CP_WAIT0();
    __syncthreads();

    for (int c = 0; c < 4; c++) {
        const int cur = c & 1, nxt = cur ^ 1;
        const bool more = (c + 1 < 4);
        if (more) loadAB(c + 1, nxt);

        #pragma unroll
        for (int kk = 0; kk < 4; kk++) {
            uint32_t ah[2][4];
            #pragma unroll
            for (int mt = 0; mt < 2; mt++) {
                uint32_t eo = (uint32_t)((a_m + mt*16) * NLD + kk*16 + a_k) * 2;
                LDSM_X4(ah[mt][0], ah[mt][1], ah[mt][2], ah[mt][3], sb + NS_A(cur) + eo);
            }
            #pragma unroll
            for (int g = 0; g < 4; g++) {
                uint32_t eo = (uint32_t)((b_n + g*16) * NLD + kk*16 + b_k) * 2;
                uint32_t bh[2][2];
                LDSM_X4(bh[0][0], bh[0][1], bh[1][0], bh[1][1], sb + NS_B(cur) + eo);
                #pragma unroll
                for (int mt = 0; mt < 2; mt++) {
                    #pragma unroll
                    for (int j = 0; j < 2; j++)
                        MMA_F16(acc[mt][g*2 + j], ah[mt], bh[j]);
                }
            }
        }
        if (more) CP_WAIT0();
        __syncthreads();
    }

    const int lr = lane >> 2;
    const int lc = (lane & 3) * 2;
    #pragma unroll
    for (int mt = 0; mt < 2; mt++) {
        int mrow0 = m0 + wm + mt*16 + lr;
        int mrow1 = mrow0 + 8;
        #pragma unroll
        for (int nt = 0; nt < 8; nt++) {
            int col = n0 + wn + nt*8 + lc;
            float2 bv = *(const float2*)(b2 + col);
            float2 r0 = *(const float2*)(H + (size_t)mrow0*DD + col);
            float2 r1 = *(const float2*)(H + (size_t)mrow1*DD + col);
            float2 o0, o1;
            o0.x = acc[mt][nt][0] + bv.x + r0.x;
            o0.y = acc[mt][nt][1] + bv.y + r0.y;
            o1.x = acc[mt][nt][2] + bv.x + r1.x;
            o1.y = acc[mt][nt][3] + bv.y + r1.y;
            *(float2*)(out + (size_t)mrow0*DD + col) = o0;
            *(float2*)(out + (size_t)mrow1*DD + col) = o1;
        }
    }
}

// ---------------- launch ----------------
extern "C" void kernel_launch(void* const* d_in, const int* in_sizes, int n_in,
                              void* d_out, int out_size) {
    (void)in_sizes; (void)n_in; (void)out_size;
    const float* H    = (const float*)d_in[0];
    const int*   pid  = (const int*)  d_in[1];
    const float* ln1g = (const float*)d_in[2];
    const float* ln1b = (const float*)d_in[3];
    const float* Wq   = (const float*)d_in[4];
    const float* bq   = (const float*)d_in[5];
    const float* Wk   = (const float*)d_in[6];
    const float* bk   = (const float*)d_in[7];
    const float* Wv   = (const float*)d_in[8];
    const float* bv   = (const float*)d_in[9];
    const float* Wo   = (const float*)d_in[10];
    const float* bo   = (const float*)d_in[11];
    const float* ln2g = (const float*)d_in[12];
    const float* ln2b = (const float*)d_in[13];
    const float* fW1  = (const float*)d_in[14];
    const float* fb1  = (const float*)d_in[15];
    const float* fW2  = (const float*)d_in[16];
    const float* fb2  = (const float*)d_in[17];
    const float* mW1  = (const float*)d_in[18];
    const float* mb1  = (const float*)d_in[19];
    const float* mW2  = (const float*)d_in[20];
    const float* mb2  = (const float*)d_in[21];

    float* out = (float*)d_out;
    float* psu = out + (size_t)SS*NN*DD;

    float *p_x, *p_y, *p_qkv, *p_attn, *p_x2, *p_h, *p_p2, *p_bqkv;
    __half *p_wqkvf, *p_wof, *p_f1f, *p_f2f, *p_p2f;
    cudaGetSymbolAddress((void**)&p_x,     g_x);
    cudaGetSymbolAddress((void**)&p_y,     g_y);
    cudaGetSymbolAddress((void**)&p_qkv,   g_qkv);
    cudaGetSymbolAddress((void**)&p_attn,  g_attn);
    cudaGetSymbolAddress((void**)&p_x2,    g_x2);
    cudaGetSymbolAddress((void**)&p_h,     g_h);
    cudaGetSymbolAddress((void**)&p_p2,    g_p2);
    cudaGetSymbolAddress((void**)&p_bqkv,  g_bqkv);
    cudaGetSymbolAddress((void**)&p_wqkvf, g_wqkvf);
    cudaGetSymbolAddress((void**)&p_wof,   g_wof);
    cudaGetSymbolAddress((void**)&p_f1f,   g_f1f);
    cudaGetSymbolAddress((void**)&p_f2f,   g_f2f);
    cudaGetSymbolAddress((void**)&p_p2f,   g_p2f);

    static int init_done = 0;
    if (!init_done) {
        cudaFuncSetAttribute(k_mma_p,   cudaFuncAttributeMaxDynamicSharedMemorySize, QSM_TOTAL);
        cudaFuncSetAttribute(k_mma_p64, cudaFuncAttributeMaxDynamicSharedMemorySize, P64_TOTAL);
        cudaFuncSetAttribute(k_node1,   cudaFuncAttributeMaxDynamicSharedMemorySize, NS_TOTAL);
        cudaFuncSetAttribute(k_node2,   cudaFuncAttributeMaxDynamicSharedMemorySize, NS_TOTAL);
        init_done = 1;
    }

    // 1) weight prep + pooling (count-sort, LN1 fused into patchsum)
    k_prep_w<<<3072, 256>>>(Wq, Wk, Wv, bq, bk, bv, Wo, fW1, fW2, mW1, mW2);
    k_count<<<SS*NN/256, 256>>>(pid);
    k_scan<<<1, 256>>>();
    k_scatter<<<SS*NN/256, 256>>>(pid);
    k_patchsum<<<SS*KK, 256>>>(H, ln1g, ln1b);

    // 2) patch transformer
    k_mma_p<<<dim3(QKVW/64, (SS*KK)/128), 256, QSM_TOTAL>>>(
        p_y, p_wqkvf, p_qkv, DD, QKVW, 6, p_bqkv, nullptr);
    k_kvsum<<<SS*NHH, 256>>>();
    k_attn<<<SS*KK, 256>>>();
    k_mma_p64<<<dim3(DD/64, (SS*KK)/64), 128, P64_TOTAL>>>(
        p_attn, p_wof, p_x2, DD, DD, 2, bo, p_x);
    k_ln<<<SS*KK, 256>>>(p_x2, ln2g, ln2b, p_y);
    k_mma_p<<<dim3(FF/64, (SS*KK)/128), 256, QSM_TOTAL>>>(
        p_y, p_f1f, p_h, DD, FF, 5, fb1, nullptr);
    k_mma_p64<<<dim3(DD/64, (SS*KK)/64), 128, P64_TOTAL>>>(
        p_h, p_f2f, psu, FF, DD, 2, fb2, p_x2);

    // 3) node MLP: p2 precompute (M64), then fp16 node GEMMs (K-chunk 64)
    k_mma_p64<<<dim3(DD/64, (SS*KK)/64), 128, P64_TOTAL>>>(
        psu, p_p2f, p_p2, DD, DD, 0, mb1, nullptr);
    dim3 gb(DD/128, (SS*NN)/128);
    k_node1<<<gb, 256, NS_TOTAL>>>(H, p_p2, pid);
    k_node2<<<gb, 256, NS_TOTAL>>>(H, mb2, out);
}